// round 9
// baseline (speedup 1.0000x reference)
#include <cuda_runtime.h>
#include <cstdint>

#define BATCH 4
#define CH    512
#define NPTS  4096
#define MROWS (BATCH * NPTS)   // 16384
#define KNN   5
#define KDIM  (2 * CH)         // 1024
#define QMAXF 16256.0f         // 127*128

// ================= PTX helpers (baseline ISA only) =========
__device__ __forceinline__ uint32_t smem_u32(const void* p) {
    return (uint32_t)__cvta_generic_to_shared((void*)p);
}
#define SWZ64(o) ((o) ^ (((o) >> 2) & 0x30))

__device__ __forceinline__ void ldsm_x4(uint32_t (&r)[4], uint32_t addr) {
    asm volatile("ldmatrix.sync.aligned.m8n8.x4.shared.b16 {%0,%1,%2,%3}, [%4];"
                 : "=r"(r[0]), "=r"(r[1]), "=r"(r[2]), "=r"(r[3]) : "r"(addr));
}
__device__ __forceinline__ void imma16832(int (&c)[4], const uint32_t (&a)[4],
                                          uint32_t b0, uint32_t b1) {
    asm volatile("mma.sync.aligned.m16n8k32.row.col.s32.s8.s8.s32 "
                 "{%0,%1,%2,%3}, {%4,%5,%6,%7}, {%8,%9}, {%0,%1,%2,%3};"
                 : "+r"(c[0]), "+r"(c[1]), "+r"(c[2]), "+r"(c[3])
                 : "r"(a[0]), "r"(a[1]), "r"(a[2]), "r"(a[3]), "r"(b0), "r"(b1));
}
#define CP_ASYNC16(dst, src) \
    asm volatile("cp.async.cg.shared.global [%0], [%1], 16;" :: "r"(dst), "l"(src))
#define CP_COMMIT() asm volatile("cp.async.commit_group;" ::: "memory")
#define CP_WAIT2()  asm volatile("cp.async.wait_group 2;" ::: "memory")
#define CP_WAIT1()  asm volatile("cp.async.wait_group 1;" ::: "memory")
#define CP_WAIT0()  asm volatile("cp.async.wait_group 0;" ::: "memory")

// ================= scratch =================
__device__ float g_xt[(size_t)MROWS * CH];
__device__ float g_y[(size_t)MROWS * CH];
__device__ float g_h[(size_t)MROWS * (CH / 2)];
__device__ int   g_idx[MROWS * KNN];
__device__ float g_sum[CH];
__device__ float g_sumsq[CH];

__device__ __align__(16) int8_t g_Aqh[(size_t)MROWS * KDIM];
__device__ __align__(16) int8_t g_Aql[(size_t)MROWS * KDIM];
__device__ float g_sA[MROWS];
__device__ __align__(16) int8_t g_Xqh[(size_t)MROWS * CH];
__device__ __align__(16) int8_t g_Xql[(size_t)MROWS * CH];
__device__ float g_sX[MROWS];
__device__ __align__(16) int8_t g_Wqh[(size_t)3 * CH * KDIM];
__device__ __align__(16) int8_t g_Wql[(size_t)3 * CH * KDIM];
__device__ float g_sW[3 * CH];
__device__ __align__(16) int8_t g_Cqh[(size_t)(CH / 2) * CH];
__device__ __align__(16) int8_t g_Cql[(size_t)(CH / 2) * CH];
__device__ float g_sC[CH / 2];

__device__ __forceinline__ void quant_pair(float v, float inv, int8_t& h8, int8_t& l8) {
    int q = __float2int_rn(v * inv);
    int ah = (q + 64) >> 7;       // round-to-nearest q/128
    int al = q - (ah << 7);
    h8 = (int8_t)ah; l8 = (int8_t)al;
}

// block-wide amax (128 threads). wsm must have >=4 floats.
__device__ __forceinline__ float block_amax(float v, float* wsm, int tid) {
#pragma unroll
    for (int off = 16; off; off >>= 1) v = fmaxf(v, __shfl_xor_sync(0xffffffffu, v, off));
    if ((tid & 31) == 0) wsm[tid >> 5] = v;
    __syncthreads();
    return fmaxf(fmaxf(wsm[0], wsm[1]), fmaxf(wsm[2], wsm[3]));
}

// ---------------- transpose: x [B,C,N] -> g_xt [B*N, C] ----------------
__global__ void transpose_kernel(const float* __restrict__ x) {
    __shared__ float tile[32][33];
    int b = blockIdx.z;
    int n0 = blockIdx.x * 32, c0 = blockIdx.y * 32;
    int tx = threadIdx.x, ty = threadIdx.y;
#pragma unroll
    for (int i = 0; i < 4; i++) {
        int c = c0 + ty + i * 8;
        tile[ty + i * 8][tx] = x[((size_t)(b * CH + c)) * NPTS + n0 + tx];
    }
    __syncthreads();
#pragma unroll
    for (int i = 0; i < 4; i++) {
        int n = n0 + ty + i * 8;
        g_xt[((size_t)(b * NPTS + n)) * CH + c0 + tx] = tile[tx][ty + i * 8];
    }
}

// ---------------- KNN (bit-exact vs reference; DO NOT TOUCH) ----------------
#define LTC(da, ia, db, ib) ((da) < (db) || ((da) == (db) && (ia) < (ib)))

__global__ void knn_kernel(const float* __restrict__ pos) {
    __shared__ float sx[NPTS];
    __shared__ float sy[NPTS];
    __shared__ float sd[NPTS];
    int b = blockIdx.y;
    const float* p = pos + (size_t)b * NPTS * 2;
    for (int j = threadIdx.x; j < NPTS; j += blockDim.x) {
        float xx = p[2 * j], yy = p[2 * j + 1];
        sx[j] = xx; sy[j] = yy;
        sd[j] = __fadd_rn(__fmul_rn(xx, xx), __fmul_rn(yy, yy));  // add-form d2
    }
    __syncthreads();

    int warp = threadIdx.x >> 5, lane = threadIdx.x & 31;
    int q = blockIdx.x * (blockDim.x >> 5) + warp;

    float xi = sx[q], yi = sy[q], d2i = sd[q];
    const float INF = __int_as_float(0x7f800000);
    float d0 = INF, d1 = INF, d2 = INF, d3 = INF, d4 = INF;
    int   i0 = 0x7fffffff, i1 = 0x7fffffff, i2 = 0x7fffffff, i3 = 0x7fffffff, i4 = 0x7fffffff;

    for (int j = lane; j < NPTS; j += 32) {
        float dot  = __fmaf_rn(yi, sy[j], __fmul_rn(xi, sx[j]));  // fma-form dot
        float dist = __fadd_rn(__fadd_rn(d2i, sd[j]), -__fmul_rn(2.0f, dot));
        if (LTC(dist, j, d4, i4)) {
            d4 = dist; i4 = j;
            if (LTC(d4, i4, d3, i3)) { float tf = d3; d3 = d4; d4 = tf; int ti = i3; i3 = i4; i4 = ti; }
            if (LTC(d3, i3, d2, i2)) { float tf = d2; d2 = d3; d3 = tf; int ti = i2; i2 = i3; i3 = ti; }
            if (LTC(d2, i2, d1, i1)) { float tf = d1; d1 = d2; d2 = tf; int ti = i1; i1 = i2; i2 = ti; }
            if (LTC(d1, i1, d0, i0)) { float tf = d0; d0 = d1; d1 = tf; int ti = i0; i0 = i1; i1 = ti; }
        }
    }
#pragma unroll
    for (int k = 0; k < KNN; k++) {
        float od = d0; int oi = i0;
#pragma unroll
        for (int off = 16; off; off >>= 1) {
            float td = __shfl_down_sync(0xffffffffu, od, off);
            int   ti = __shfl_down_sync(0xffffffffu, oi, off);
            if (LTC(td, ti, od, oi)) { od = td; oi = ti; }
        }
        od = __shfl_sync(0xffffffffu, od, 0);
        oi = __shfl_sync(0xffffffffu, oi, 0);
        if (oi == i0) {
            d0 = d1; i0 = i1; d1 = d2; i1 = i2; d2 = d3; i2 = i3; d3 = d4; i3 = i4;
            d4 = INF; i4 = 0x7fffffff;
        }
        if (lane == 0) g_idx[((size_t)(b * NPTS + q)) * KNN + k] = oi;
    }
}

// ---------------- feat_q (layer 1): gather + maxrel -> int8 hi/lo + row scale ----
__global__ void feat_q() {
    __shared__ float sf[KDIM];
    __shared__ float wsm[4];
    __shared__ int nb[KNN];
    int r = blockIdx.x, tid = threadIdx.x;
    if (tid < KNN) nb[tid] = (r >> 12) * NPTS + g_idx[r * KNN + tid];
    __syncthreads();
    int n0 = nb[0], n1 = nb[1], n2 = nb[2], n3 = nb[3], n4 = nb[4];
    const float* xr = g_xt + (size_t)r * CH;
    float am = 0.f;
    for (int c = tid; c < CH; c += 128) {
        float s = xr[c];
        float m = g_xt[(size_t)n0 * CH + c] - s;
        m = fmaxf(m, g_xt[(size_t)n1 * CH + c] - s);
        m = fmaxf(m, g_xt[(size_t)n2 * CH + c] - s);
        m = fmaxf(m, g_xt[(size_t)n3 * CH + c] - s);
        m = fmaxf(m, g_xt[(size_t)n4 * CH + c] - s);
        sf[2 * c] = s; sf[2 * c + 1] = m;
        am = fmaxf(am, fmaxf(fabsf(s), fabsf(m)));
    }
    am = block_amax(am, wsm, tid);
    float inv = (am > 0.f) ? QMAXF / am : 0.f;
    if (tid == 0) g_sA[r] = am / QMAXF;
    __syncthreads();
    int8_t* dh = g_Aqh + (size_t)r * KDIM;
    int8_t* dl = g_Aql + (size_t)r * KDIM;
    for (int e = tid; e < KDIM; e += 128) quant_pair(sf[e], inv, dh[e], dl[e]);
}

// ---------------- bnfeat_q (layers 2,3): BN+relu on the fly, gather+maxrel, quant --
__global__ void bnfeat_q(const float* __restrict__ gamma, const float* __restrict__ beta) {
    __shared__ float sf[KDIM];
    __shared__ float wsm[4];
    __shared__ int nb[KNN];
    int r = blockIdx.x, tid = threadIdx.x;
    if (tid < KNN) nb[tid] = (r >> 12) * NPTS + g_idx[r * KNN + tid];
    __syncthreads();
    int n0 = nb[0], n1 = nb[1], n2 = nb[2], n3 = nb[3], n4 = nb[4];
    const float* yr = g_y + (size_t)r * CH;
    const float invM = 1.0f / (float)MROWS;
    float am = 0.f;
    for (int c = tid; c < CH; c += 128) {
        float mean = g_sum[c] * invM;
        float var  = g_sumsq[c] * invM - mean * mean;
        float rs = rsqrtf(var + 1e-5f);
        float gm = gamma[c], bt = beta[c];
        float s  = fmaxf((yr[c] - mean) * rs * gm + bt, 0.f);
        float a0 = fmaxf((g_y[(size_t)n0 * CH + c] - mean) * rs * gm + bt, 0.f);
        float a1 = fmaxf((g_y[(size_t)n1 * CH + c] - mean) * rs * gm + bt, 0.f);
        float a2 = fmaxf((g_y[(size_t)n2 * CH + c] - mean) * rs * gm + bt, 0.f);
        float a3 = fmaxf((g_y[(size_t)n3 * CH + c] - mean) * rs * gm + bt, 0.f);
        float a4 = fmaxf((g_y[(size_t)n4 * CH + c] - mean) * rs * gm + bt, 0.f);
        float m = fmaxf(fmaxf(fmaxf(a0 - s, a1 - s), fmaxf(a2 - s, a3 - s)), a4 - s);
        sf[2 * c] = s; sf[2 * c + 1] = m;
        am = fmaxf(am, fmaxf(fabsf(s), fabsf(m)));
    }
    am = block_amax(am, wsm, tid);
    float inv = (am > 0.f) ? QMAXF / am : 0.f;
    if (tid == 0) g_sA[r] = am / QMAXF;
    __syncthreads();
    int8_t* dh = g_Aqh + (size_t)r * KDIM;
    int8_t* dl = g_Aql + (size_t)r * KDIM;
    for (int e = tid; e < KDIM; e += 128) quant_pair(sf[e], inv, dh[e], dl[e]);
}

// ---------------- quant_cls: BN+relu(layer3) -> int8 X rows for classifier -------
__global__ void quant_cls(const float* __restrict__ gamma, const float* __restrict__ beta) {
    __shared__ float sf[CH];
    __shared__ float wsm[4];
    int r = blockIdx.x, tid = threadIdx.x;
    const float* yr = g_y + (size_t)r * CH;
    const float invM = 1.0f / (float)MROWS;
    float am = 0.f;
    for (int c = tid; c < CH; c += 128) {
        float mean = g_sum[c] * invM;
        float var  = g_sumsq[c] * invM - mean * mean;
        float v = fmaxf((yr[c] - mean) * rsqrtf(var + 1e-5f) * gamma[c] + beta[c], 0.f);
        sf[c] = v;
        am = fmaxf(am, fabsf(v));
    }
    am = block_amax(am, wsm, tid);
    float inv = (am > 0.f) ? QMAXF / am : 0.f;
    if (tid == 0) g_sX[r] = am / QMAXF;
    __syncthreads();
    int8_t* dh = g_Xqh + (size_t)r * CH;
    int8_t* dl = g_Xql + (size_t)r * CH;
    for (int e = tid; e < CH; e += 128) quant_pair(sf[e], inv, dh[e], dl[e]);
}

// ---------------- weight quantization: one block per output-channel row ----------
__global__ void wsplit_q(const float* __restrict__ w1, const float* __restrict__ w2,
                         const float* __restrict__ w3, const float* __restrict__ wc1) {
    __shared__ float wsm[4];
    int b = blockIdx.x, tid = threadIdx.x;
    const float* src; int8_t *dh, *dl; float* sout; int L;
    if (b < 3 * CH) {
        int layer = b >> 9;
        int row = b & (CH - 1);
        src = (layer == 0 ? w1 : layer == 1 ? w2 : w3) + (size_t)row * KDIM;
        dh = g_Wqh + (size_t)b * KDIM; dl = g_Wql + (size_t)b * KDIM;
        sout = &g_sW[b]; L = KDIM;
    } else {
        int row = b - 3 * CH;
        src = wc1 + (size_t)row * CH;
        dh = g_Cqh + (size_t)row * CH; dl = g_Cql + (size_t)row * CH;
        sout = &g_sC[row]; L = CH;
    }
    float am = 0.f;
    for (int e = tid; e < L; e += 128) am = fmaxf(am, fabsf(src[e]));
    am = block_amax(am, wsm, tid);
    float inv = (am > 0.f) ? QMAXF / am : 0.f;
    if (tid == 0) *sout = am / QMAXF;
    for (int e = tid; e < L; e += 128) quant_pair(src[e], inv, dh[e], dl[e]);
}

__global__ void zero_stats() {
    g_sum[threadIdx.x] = 0.f;
    g_sumsq[threadIdx.x] = 0.f;
}

// ================= IMMA 15-bit split GEMM, 128x128 tile, 3-stage, fused stats ====
// C[r][c] = sA[r]*sB[c]*(16384*acc_hi + 128*acc_mid) + bias; acc from s8 mma k32.
// 8 warps (2M x 4N), warp 64x32. K chunks of 64 int8. Single K pass (hi+mid fused).
#define TILE_B 8192
#define STAGE_BYTES (4 * TILE_B)                 // Ah, Al, Bh, Bl = 32 KB
#define SMEM_GEMM_BYTES (3 * STAGE_BYTES)        // 96 KB

template <int RELU, int STATS>
__global__ void __launch_bounds__(256) imma_gemm(
    const int8_t* __restrict__ Ah, const int8_t* __restrict__ Al,
    const int8_t* __restrict__ Bh, const int8_t* __restrict__ Bl,
    const float* __restrict__ sA, const float* __restrict__ sB,
    const float* __restrict__ bias, float* __restrict__ C, int Kd, int Nn) {
    extern __shared__ char smem[];
    uint32_t sb = smem_u32(smem);
    int tid = threadIdx.x, lane = tid & 31, wid = tid >> 5;
    int wm = wid & 1, wn = wid >> 1;
    int row0 = blockIdx.y * 128, col0 = blockIdx.x * 128;
    int NIT = Kd >> 6;

    int hi[4][4][4], md[4][4][4];
#pragma unroll
    for (int mi = 0; mi < 4; mi++)
#pragma unroll
        for (int ni = 0; ni < 4; ni++)
#pragma unroll
            for (int j = 0; j < 4; j++) { hi[mi][ni][j] = 0; md[mi][ni][j] = 0; }

    const int8_t* tp0 = Ah + (size_t)row0 * Kd;
    const int8_t* tp1 = Al + (size_t)row0 * Kd;
    const int8_t* tp2 = Bh + (size_t)col0 * Kd;
    const int8_t* tp3 = Bl + (size_t)col0 * Kd;

    auto load_chunk = [&](int kc, int st) {
        uint32_t base = sb + st * STAGE_BYTES;
        const int8_t* tps[4] = {tp0, tp1, tp2, tp3};
#pragma unroll
        for (int t = 0; t < 4; t++) {
            const int8_t* p = tps[t] + kc * 64;
            uint32_t tb = base + t * TILE_B;
#pragma unroll
            for (int i = 0; i < 2; i++) {
                int e = tid + i * 256;
                int r = e >> 2, g = e & 3;
                CP_ASYNC16(tb + SWZ64((uint32_t)(r * 64 + g * 16)),
                           p + (size_t)r * Kd + g * 16);
            }
        }
        CP_COMMIT();
    };

    load_chunk(0, 0);
    load_chunk(1, 1);

    for (int it = 0; it < NIT; it++) {
        int s = it % 3;
        if (it + 2 < NIT) { load_chunk(it + 2, (it + 2) % 3); CP_WAIT2(); }
        else if (it + 1 < NIT) { CP_WAIT1(); }
        else { CP_WAIT0(); }
        __syncthreads();

        uint32_t ahb = sb + s * STAGE_BYTES;
        uint32_t alb = ahb + TILE_B;
        uint32_t bhb = ahb + 2 * TILE_B;
        uint32_t blb = ahb + 3 * TILE_B;
#pragma unroll
        for (int kk = 0; kk < 2; kk++) {
            uint32_t ahf[4][4], alf[4][4];
#pragma unroll
            for (int mi = 0; mi < 4; mi++) {
                int r = wm * 64 + mi * 16 + (lane & 15);
                uint32_t off = SWZ64((uint32_t)(r * 64 + kk * 32 + (lane >> 4) * 16));
                ldsm_x4(ahf[mi], ahb + off);
                ldsm_x4(alf[mi], alb + off);
            }
            uint32_t bhf[2][4], blf[2][4];
#pragma unroll
            for (int p = 0; p < 2; p++) {
                int r = wn * 32 + p * 16 + (lane & 15);
                uint32_t off = SWZ64((uint32_t)(r * 64 + kk * 32 + (lane >> 4) * 16));
                ldsm_x4(bhf[p], bhb + off);
                ldsm_x4(blf[p], blb + off);
            }
#pragma unroll
            for (int mi = 0; mi < 4; mi++) {
#pragma unroll
                for (int ni = 0; ni < 4; ni++) {
                    int p = ni >> 1, o = ni & 1;
                    imma16832(hi[mi][ni], ahf[mi], bhf[p][o], bhf[p][o + 2]);
                    imma16832(md[mi][ni], ahf[mi], blf[p][o], blf[p][o + 2]);
                    imma16832(md[mi][ni], alf[mi], bhf[p][o], bhf[p][o + 2]);
                }
            }
        }
        __syncthreads();
    }

    // epilogue: dequant, +bias, optional relu, store; optional fused column stats
    float s_[4][2], q_[4][2];
    if (STATS) {
#pragma unroll
        for (int ni = 0; ni < 4; ni++) { s_[ni][0] = s_[ni][1] = q_[ni][0] = q_[ni][1] = 0.f; }
    }
#pragma unroll
    for (int mi = 0; mi < 4; mi++) {
        int r1 = row0 + wm * 64 + mi * 16 + (lane >> 2);
        int r2 = r1 + 8;
        float sa1 = sA[r1], sa2 = sA[r2];
#pragma unroll
        for (int ni = 0; ni < 4; ni++) {
            int col = col0 + wn * 32 + ni * 8 + (lane & 3) * 2;
            float sb0 = sB[col], sb1 = sB[col + 1];
            float b0 = bias[col], b1 = bias[col + 1];
            float f0 = fmaf(16384.f, (float)hi[mi][ni][0], 128.f * (float)md[mi][ni][0]);
            float f1 = fmaf(16384.f, (float)hi[mi][ni][1], 128.f * (float)md[mi][ni][1]);
            float f2 = fmaf(16384.f, (float)hi[mi][ni][2], 128.f * (float)md[mi][ni][2]);
            float f3 = fmaf(16384.f, (float)hi[mi][ni][3], 128.f * (float)md[mi][ni][3]);
            float v0 = fmaf(sa1 * sb0, f0, b0);
            float v1 = fmaf(sa1 * sb1, f1, b1);
            float v2 = fmaf(sa2 * sb0, f2, b0);
            float v3 = fmaf(sa2 * sb1, f3, b1);
            if (RELU) {
                v0 = fmaxf(v0, 0.f); v1 = fmaxf(v1, 0.f);
                v2 = fmaxf(v2, 0.f); v3 = fmaxf(v3, 0.f);
            }
            if (STATS) {
                s_[ni][0] += v0 + v2; s_[ni][1] += v1 + v3;
                q_[ni][0] += v0 * v0 + v2 * v2; q_[ni][1] += v1 * v1 + v3 * v3;
            }
            *(float2*)(C + (size_t)r1 * Nn + col) = make_float2(v0, v1);
            *(float2*)(C + (size_t)r2 * Nn + col) = make_float2(v2, v3);
        }
    }
    if (STATS) {
#pragma unroll
        for (int ni = 0; ni < 4; ni++) {
#pragma unroll
            for (int j = 0; j < 2; j++) {
#pragma unroll
                for (int off = 4; off <= 16; off <<= 1) {
                    s_[ni][j] += __shfl_xor_sync(0xffffffffu, s_[ni][j], off);
                    q_[ni][j] += __shfl_xor_sync(0xffffffffu, q_[ni][j], off);
                }
            }
        }
        if ((lane >> 2) == 0) {
#pragma unroll
            for (int ni = 0; ni < 4; ni++) {
                int col = col0 + wn * 32 + ni * 8 + (lane & 3) * 2;
                atomicAdd(&g_sum[col],     s_[ni][0]);
                atomicAdd(&g_sum[col + 1], s_[ni][1]);
                atomicAdd(&g_sumsq[col],     q_[ni][0]);
                atomicAdd(&g_sumsq[col + 1], q_[ni][1]);
            }
        }
    }
}

// ---------------- final tiny GEMM: out[M,5] = h[M,256] @ Wc2[5,256]^T + bc2 -----
__global__ void final_kernel(const float* __restrict__ Wc2, const float* __restrict__ bc2,
                             float* __restrict__ out) {
    __shared__ float w[5 * 256];
    for (int i = threadIdx.x; i < 5 * 256; i += blockDim.x) w[i] = Wc2[i];
    __syncthreads();
    int warp = threadIdx.x >> 5, lane = threadIdx.x & 31;
    int r = blockIdx.x * (blockDim.x >> 5) + warp;
    const float* h = g_h + (size_t)r * 256;
    float a0 = 0, a1 = 0, a2 = 0, a3 = 0, a4 = 0;
    for (int c = lane; c < 256; c += 32) {
        float hv = h[c];
        a0 = fmaf(hv, w[0 * 256 + c], a0);
        a1 = fmaf(hv, w[1 * 256 + c], a1);
        a2 = fmaf(hv, w[2 * 256 + c], a2);
        a3 = fmaf(hv, w[3 * 256 + c], a3);
        a4 = fmaf(hv, w[4 * 256 + c], a4);
    }
#pragma unroll
    for (int off = 16; off; off >>= 1) {
        a0 += __shfl_xor_sync(0xffffffffu, a0, off);
        a1 += __shfl_xor_sync(0xffffffffu, a1, off);
        a2 += __shfl_xor_sync(0xffffffffu, a2, off);
        a3 += __shfl_xor_sync(0xffffffffu, a3, off);
        a4 += __shfl_xor_sync(0xffffffffu, a4, off);
    }
    if (lane == 0) {
        float* o = out + (size_t)r * 5;
        o[0] = a0 + bc2[0];
        o[1] = a1 + bc2[1];
        o[2] = a2 + bc2[2];
        o[3] = a3 + bc2[3];
        o[4] = a4 + bc2[4];
    }
}

// ---------------- launch ----------------
extern "C" void kernel_launch(void* const* d_in, const int* in_sizes, int n_in,
                              void* d_out, int out_size) {
    const float* x    = (const float*)d_in[0];
    const float* pos  = (const float*)d_in[1];
    const float* W[3]  = {(const float*)d_in[2], (const float*)d_in[6], (const float*)d_in[10]};
    const float* bb[3] = {(const float*)d_in[3], (const float*)d_in[7], (const float*)d_in[11]};
    const float* gg[3] = {(const float*)d_in[4], (const float*)d_in[8], (const float*)d_in[12]};
    const float* be[3] = {(const float*)d_in[5], (const float*)d_in[9], (const float*)d_in[13]};
    const float* Wc1 = (const float*)d_in[14];
    const float* bc1 = (const float*)d_in[15];
    const float* Wc2 = (const float*)d_in[16];
    const float* bc2 = (const float*)d_in[17];
    float* out = (float*)d_out;

    float *p_y, *p_h, *p_sA, *p_sX, *p_sW, *p_sC;
    int8_t *p_Aqh, *p_Aql, *p_Xqh, *p_Xql, *p_Wqh, *p_Wql, *p_Cqh, *p_Cql;
    cudaGetSymbolAddress((void**)&p_y, g_y);
    cudaGetSymbolAddress((void**)&p_h, g_h);
    cudaGetSymbolAddress((void**)&p_sA, g_sA);
    cudaGetSymbolAddress((void**)&p_sX, g_sX);
    cudaGetSymbolAddress((void**)&p_sW, g_sW);
    cudaGetSymbolAddress((void**)&p_sC, g_sC);
    cudaGetSymbolAddress((void**)&p_Aqh, g_Aqh);
    cudaGetSymbolAddress((void**)&p_Aql, g_Aql);
    cudaGetSymbolAddress((void**)&p_Xqh, g_Xqh);
    cudaGetSymbolAddress((void**)&p_Xql, g_Xql);
    cudaGetSymbolAddress((void**)&p_Wqh, g_Wqh);
    cudaGetSymbolAddress((void**)&p_Wql, g_Wql);
    cudaGetSymbolAddress((void**)&p_Cqh, g_Cqh);
    cudaGetSymbolAddress((void**)&p_Cql, g_Cql);

    cudaFuncSetAttribute(imma_gemm<0, 1>, cudaFuncAttributeMaxDynamicSharedMemorySize, SMEM_GEMM_BYTES);
    cudaFuncSetAttribute(imma_gemm<1, 0>, cudaFuncAttributeMaxDynamicSharedMemorySize, SMEM_GEMM_BYTES);

    transpose_kernel<<<dim3(NPTS / 32, CH / 32, BATCH), dim3(32, 8)>>>(x);
    knn_kernel<<<dim3(NPTS / 8, BATCH), 256>>>(pos);
    wsplit_q<<<3 * CH + CH / 2, 128>>>(W[0], W[1], W[2], Wc1);

    for (int i = 0; i < 3; i++) {
        if (i == 0) feat_q<<<MROWS, 128>>>();
        else        bnfeat_q<<<MROWS, 128>>>(gg[i - 1], be[i - 1]);
        zero_stats<<<1, CH>>>();
        imma_gemm<0, 1><<<dim3(CH / 128, MROWS / 128), 256, SMEM_GEMM_BYTES>>>(
            p_Aqh, p_Aql, p_Wqh + (size_t)i * CH * KDIM, p_Wql + (size_t)i * CH * KDIM,
            p_sA, p_sW + (size_t)i * CH, bb[i], p_y, KDIM, CH);
    }

    // classifier: quantize bn+relu(layer3), then h = relu(X @ Wc1^T + bc1)
    quant_cls<<<MROWS, 128>>>(gg[2], be[2]);
    imma_gemm<1, 0><<<dim3((CH / 2) / 128, MROWS / 128), 256, SMEM_GEMM_BYTES>>>(
        p_Xqh, p_Xql, p_Cqh, p_Cql, p_sX, p_sC, bc1, p_h, CH, CH / 2);
    final_kernel<<<MROWS / 8, 256>>>(Wc2, bc2, out);
}

// round 10
// speedup vs baseline: 2.1724x; 2.1724x over previous
#include <cuda_runtime.h>
#include <cuda_bf16.h>
#include <cstdint>

#define BATCH 4
#define CH    512
#define NPTS  4096
#define MROWS (BATCH * NPTS)   // 16384
#define KNN   5
#define KDIM  (2 * CH)         // 1024

// ================= PTX helpers (baseline ISA only — no sm_103a features) =========
__device__ __forceinline__ uint32_t smem_u32(const void* p) {
    return (uint32_t)__cvta_generic_to_shared((void*)p);
}
#define SWZ(o) ((o) ^ (((o) >> 3) & 0x70))

__device__ __forceinline__ void ldsm_x4(uint32_t (&r)[4], uint32_t addr) {
    asm volatile("ldmatrix.sync.aligned.m8n8.x4.shared.b16 {%0,%1,%2,%3}, [%4];"
                 : "=r"(r[0]), "=r"(r[1]), "=r"(r[2]), "=r"(r[3]) : "r"(addr));
}
__device__ __forceinline__ void ldsm_x2(uint32_t (&r)[2], uint32_t addr) {
    asm volatile("ldmatrix.sync.aligned.m8n8.x2.shared.b16 {%0,%1}, [%2];"
                 : "=r"(r[0]), "=r"(r[1]) : "r"(addr));
}
__device__ __forceinline__ void mma16816(float (&c)[4], const uint32_t (&a)[4],
                                         uint32_t b0, uint32_t b1) {
    asm volatile("mma.sync.aligned.m16n8k16.row.col.f32.bf16.bf16.f32 "
                 "{%0,%1,%2,%3}, {%4,%5,%6,%7}, {%8,%9}, {%0,%1,%2,%3};"
                 : "+f"(c[0]), "+f"(c[1]), "+f"(c[2]), "+f"(c[3])
                 : "r"(a[0]), "r"(a[1]), "r"(a[2]), "r"(a[3]), "r"(b0), "r"(b1));
}
#define CP_ASYNC16(dst, src) \
    asm volatile("cp.async.cg.shared.global [%0], [%1], 16;" :: "r"(dst), "l"(src))
#define CP_COMMIT() asm volatile("cp.async.commit_group;" ::: "memory")
#define CP_WAIT2()  asm volatile("cp.async.wait_group 2;" ::: "memory")
#define CP_WAIT1()  asm volatile("cp.async.wait_group 1;" ::: "memory")
#define CP_WAIT0()  asm volatile("cp.async.wait_group 0;" ::: "memory")

// ================= scratch (static device globals; no allocation) =================
__device__ float g_xt[(size_t)MROWS * CH];
__device__ __align__(16) __nv_bfloat16 g_Ahi[(size_t)MROWS * KDIM];
__device__ __align__(16) __nv_bfloat16 g_Alo[(size_t)MROWS * KDIM];
__device__ __align__(16) __nv_bfloat16 g_Xhi[(size_t)MROWS * CH];
__device__ __align__(16) __nv_bfloat16 g_Xlo[(size_t)MROWS * CH];
__device__ __align__(16) __nv_bfloat16 g_Whi[(size_t)3 * CH * KDIM];
__device__ __align__(16) __nv_bfloat16 g_Wlo[(size_t)3 * CH * KDIM];
__device__ __align__(16) __nv_bfloat16 g_Chi[(size_t)(CH / 2) * CH];
__device__ __align__(16) __nv_bfloat16 g_Clo[(size_t)(CH / 2) * CH];
__device__ float g_y[(size_t)MROWS * CH];
__device__ float g_h[(size_t)MROWS * (CH / 2)];
__device__ int   g_idx[MROWS * KNN];
__device__ float g_sum[CH];
__device__ float g_sumsq[CH];
__device__ __align__(16) float g_bnA[CH];   // rs * gamma
__device__ __align__(16) float g_bnB[CH];   // beta - mean * rs * gamma

__device__ __forceinline__ void split_bf16(float x, __nv_bfloat16& h, __nv_bfloat16& l) {
    h = __float2bfloat16(x);
    l = __float2bfloat16(x - __bfloat162float(h));
}
__device__ __forceinline__ uint32_t pack_pair(float s, float m, float& sl, float& ml) {
    __nv_bfloat162 v;
    v.x = __float2bfloat16(s);
    v.y = __float2bfloat16(m);
    sl = s - __bfloat162float(v.x);
    ml = m - __bfloat162float(v.y);
    return *(uint32_t*)&v;
}
__device__ __forceinline__ uint32_t pack_lo(float sl, float ml) {
    __nv_bfloat162 v;
    v.x = __float2bfloat16(sl);
    v.y = __float2bfloat16(ml);
    return *(uint32_t*)&v;
}

// ---------------- transpose: x [B,C,N] -> g_xt [B*N, C] ----------------
__global__ void transpose_kernel(const float* __restrict__ x) {
    __shared__ float tile[32][33];
    int b = blockIdx.z;
    int n0 = blockIdx.x * 32, c0 = blockIdx.y * 32;
    int tx = threadIdx.x, ty = threadIdx.y;
#pragma unroll
    for (int i = 0; i < 4; i++) {
        int c = c0 + ty + i * 8;
        tile[ty + i * 8][tx] = x[((size_t)(b * CH + c)) * NPTS + n0 + tx];
    }
    __syncthreads();
#pragma unroll
    for (int i = 0; i < 4; i++) {
        int n = n0 + ty + i * 8;
        g_xt[((size_t)(b * NPTS + n)) * CH + c0 + tx] = tile[tx][ty + i * 8];
    }
}

// ---------------- KNN (bit-exact vs reference; DO NOT TOUCH) ----------------
#define LTC(da, ia, db, ib) ((da) < (db) || ((da) == (db) && (ia) < (ib)))

__global__ void knn_kernel(const float* __restrict__ pos) {
    __shared__ float sx[NPTS];
    __shared__ float sy[NPTS];
    __shared__ float sd[NPTS];
    int b = blockIdx.y;
    const float* p = pos + (size_t)b * NPTS * 2;
    for (int j = threadIdx.x; j < NPTS; j += blockDim.x) {
        float xx = p[2 * j], yy = p[2 * j + 1];
        sx[j] = xx; sy[j] = yy;
        sd[j] = __fadd_rn(__fmul_rn(xx, xx), __fmul_rn(yy, yy));  // add-form d2
    }
    __syncthreads();

    int warp = threadIdx.x >> 5, lane = threadIdx.x & 31;
    int q = blockIdx.x * (blockDim.x >> 5) + warp;

    float xi = sx[q], yi = sy[q], d2i = sd[q];
    const float INF = __int_as_float(0x7f800000);
    float d0 = INF, d1 = INF, d2 = INF, d3 = INF, d4 = INF;
    int   i0 = 0x7fffffff, i1 = 0x7fffffff, i2 = 0x7fffffff, i3 = 0x7fffffff, i4 = 0x7fffffff;

    for (int j = lane; j < NPTS; j += 32) {
        float dot  = __fmaf_rn(yi, sy[j], __fmul_rn(xi, sx[j]));  // fma-form dot
        float dist = __fadd_rn(__fadd_rn(d2i, sd[j]), -__fmul_rn(2.0f, dot));
        if (LTC(dist, j, d4, i4)) {
            d4 = dist; i4 = j;
            if (LTC(d4, i4, d3, i3)) { float tf = d3; d3 = d4; d4 = tf; int ti = i3; i3 = i4; i4 = ti; }
            if (LTC(d3, i3, d2, i2)) { float tf = d2; d2 = d3; d3 = tf; int ti = i2; i2 = i3; i3 = ti; }
            if (LTC(d2, i2, d1, i1)) { float tf = d1; d1 = d2; d2 = tf; int ti = i1; i1 = i2; i2 = ti; }
            if (LTC(d1, i1, d0, i0)) { float tf = d0; d0 = d1; d1 = tf; int ti = i0; i0 = i1; i1 = ti; }
        }
    }
#pragma unroll
    for (int k = 0; k < KNN; k++) {
        float od = d0; int oi = i0;
#pragma unroll
        for (int off = 16; off; off >>= 1) {
            float td = __shfl_down_sync(0xffffffffu, od, off);
            int   ti = __shfl_down_sync(0xffffffffu, oi, off);
            if (LTC(td, ti, od, oi)) { od = td; oi = ti; }
        }
        od = __shfl_sync(0xffffffffu, od, 0);
        oi = __shfl_sync(0xffffffffu, oi, 0);
        if (oi == i0) {
            d0 = d1; i0 = i1; d1 = d2; i1 = i2; d2 = d3; i2 = i3; d3 = d4; i3 = i4;
            d4 = INF; i4 = 0x7fffffff;
        }
        if (lane == 0) g_idx[((size_t)(b * NPTS + q)) * KNN + k] = oi;
    }
}

// ---------------- bn coefficient precompute (1 block, 512 threads) ---------------
__global__ void bn_coef(const float* __restrict__ gamma, const float* __restrict__ beta) {
    int c = threadIdx.x;
    const float inv = 1.0f / (float)MROWS;
    float mean = g_sum[c] * inv;
    float var  = g_sumsq[c] * inv - mean * mean;
    float a = rsqrtf(var + 1e-5f) * gamma[c];
    g_bnA[c] = a;
    g_bnB[c] = beta[c] - mean * a;
}

// ---------------- feat (layer 1): gather + maxrel from fp32 g_xt, float4 ---------
__global__ void feat_kernel() {
    __shared__ int nb[KNN];
    int r = blockIdx.x, tid = threadIdx.x;   // 128 threads, c4 = tid
    if (tid < KNN) nb[tid] = (r >> 12) * NPTS + g_idx[r * KNN + tid];
    __syncthreads();
    float4 s = ((const float4*)(g_xt + (size_t)r * CH))[tid];
    float4 m = make_float4(-1e30f, -1e30f, -1e30f, -1e30f);
#pragma unroll
    for (int k = 0; k < KNN; k++) {
        float4 v = ((const float4*)(g_xt + (size_t)nb[k] * CH))[tid];
        m.x = fmaxf(m.x, v.x - s.x); m.y = fmaxf(m.y, v.y - s.y);
        m.z = fmaxf(m.z, v.z - s.z); m.w = fmaxf(m.w, v.w - s.w);
    }
    float slx, mlx, sly, mly, slz, mlz, slw, mlw;
    uint4 hi, lo;
    hi.x = pack_pair(s.x, m.x, slx, mlx);
    hi.y = pack_pair(s.y, m.y, sly, mly);
    hi.z = pack_pair(s.z, m.z, slz, mlz);
    hi.w = pack_pair(s.w, m.w, slw, mlw);
    lo.x = pack_lo(slx, mlx); lo.y = pack_lo(sly, mly);
    lo.z = pack_lo(slz, mlz); lo.w = pack_lo(slw, mlw);
    ((uint4*)(g_Ahi + (size_t)r * KDIM))[tid] = hi;
    ((uint4*)(g_Alo + (size_t)r * KDIM))[tid] = lo;
}

// ---------------- bnfeat (layers 2,3): BN(g_y)+relu on the fly, float4 -----------
__global__ void bnfeat_kernel() {
    __shared__ int nb[KNN];
    int r = blockIdx.x, tid = threadIdx.x;
    if (tid < KNN) nb[tid] = (r >> 12) * NPTS + g_idx[r * KNN + tid];
    __syncthreads();
    float4 a = ((const float4*)g_bnA)[tid];
    float4 b = ((const float4*)g_bnB)[tid];
    float4 y = ((const float4*)(g_y + (size_t)r * CH))[tid];
    float4 s;
    s.x = fmaxf(fmaf(y.x, a.x, b.x), 0.f);
    s.y = fmaxf(fmaf(y.y, a.y, b.y), 0.f);
    s.z = fmaxf(fmaf(y.z, a.z, b.z), 0.f);
    s.w = fmaxf(fmaf(y.w, a.w, b.w), 0.f);
    float4 m = make_float4(-1e30f, -1e30f, -1e30f, -1e30f);
#pragma unroll
    for (int k = 0; k < KNN; k++) {
        float4 v = ((const float4*)(g_y + (size_t)nb[k] * CH))[tid];
        m.x = fmaxf(m.x, fmaxf(fmaf(v.x, a.x, b.x), 0.f) - s.x);
        m.y = fmaxf(m.y, fmaxf(fmaf(v.y, a.y, b.y), 0.f) - s.y);
        m.z = fmaxf(m.z, fmaxf(fmaf(v.z, a.z, b.z), 0.f) - s.z);
        m.w = fmaxf(m.w, fmaxf(fmaf(v.w, a.w, b.w), 0.f) - s.w);
    }
    float slx, mlx, sly, mly, slz, mlz, slw, mlw;
    uint4 hi, lo;
    hi.x = pack_pair(s.x, m.x, slx, mlx);
    hi.y = pack_pair(s.y, m.y, sly, mly);
    hi.z = pack_pair(s.z, m.z, slz, mlz);
    hi.w = pack_pair(s.w, m.w, slw, mlw);
    lo.x = pack_lo(slx, mlx); lo.y = pack_lo(sly, mly);
    lo.z = pack_lo(slz, mlz); lo.w = pack_lo(slw, mlw);
    ((uint4*)(g_Ahi + (size_t)r * KDIM))[tid] = hi;
    ((uint4*)(g_Alo + (size_t)r * KDIM))[tid] = lo;
}

// ---------------- bn_apply for classifier (layer 3 -> Xhi/Xlo), float4 -----------
__global__ void bn_apply_cls() {
    int i4 = blockIdx.x * blockDim.x + threadIdx.x;   // float4 index
    int c4 = i4 & 127;
    float4 a = ((const float4*)g_bnA)[c4];
    float4 b = ((const float4*)g_bnB)[c4];
    float4 y = ((const float4*)g_y)[i4];
    float vx = fmaxf(fmaf(y.x, a.x, b.x), 0.f);
    float vy = fmaxf(fmaf(y.y, a.y, b.y), 0.f);
    float vz = fmaxf(fmaf(y.z, a.z, b.z), 0.f);
    float vw = fmaxf(fmaf(y.w, a.w, b.w), 0.f);
    __nv_bfloat16 hx, lx, hy, ly, hz, lz, hw, lw;
    split_bf16(vx, hx, lx); split_bf16(vy, hy, ly);
    split_bf16(vz, hz, lz); split_bf16(vw, hw, lw);
    __nv_bfloat162 h0; h0.x = hx; h0.y = hy;
    __nv_bfloat162 h1; h1.x = hz; h1.y = hw;
    __nv_bfloat162 l0; l0.x = lx; l0.y = ly;
    __nv_bfloat162 l1; l1.x = lz; l1.y = lw;
    uint2 hv = make_uint2(*(uint32_t*)&h0, *(uint32_t*)&h1);
    uint2 lv = make_uint2(*(uint32_t*)&l0, *(uint32_t*)&l1);
    ((uint2*)g_Xhi)[i4] = hv;
    ((uint2*)g_Xlo)[i4] = lv;
}

// ---------------- all weight splits in one launch ----------------
#define W_ELEMS (CH * KDIM)
#define C_ELEMS ((CH / 2) * CH)
__global__ void wsplit_all(const float* __restrict__ w1, const float* __restrict__ w2,
                           const float* __restrict__ w3, const float* __restrict__ wc1) {
    int i = blockIdx.x * blockDim.x + threadIdx.x;
    const float* src; __nv_bfloat16 *hi, *lo; int k;
    if (i < W_ELEMS)            { src = w1;  hi = g_Whi;               lo = g_Wlo;               k = i; }
    else if (i < 2 * W_ELEMS)   { src = w2;  hi = g_Whi + W_ELEMS;     lo = g_Wlo + W_ELEMS;     k = i - W_ELEMS; }
    else if (i < 3 * W_ELEMS)   { src = w3;  hi = g_Whi + 2 * W_ELEMS; lo = g_Wlo + 2 * W_ELEMS; k = i - 2 * W_ELEMS; }
    else if (i < 3 * W_ELEMS + C_ELEMS) { src = wc1; hi = g_Chi;       lo = g_Clo;               k = i - 3 * W_ELEMS; }
    else return;
    __nv_bfloat16 h, l;
    split_bf16(src[k], h, l);
    hi[k] = h; lo[k] = l;
}

__global__ void zero_stats() {
    g_sum[threadIdx.x] = 0.f;
    g_sumsq[threadIdx.x] = 0.f;
}

// ================= HMMA split-bf16 GEMM, 128x128 tile, 3-stage, 2 CTA/SM =========
// C[M,Nn] fp32 = Ahi*Bhi^T + Alo*Bhi^T + Ahi*Blo^T + bias, optional relu.
// 8 warps (2M x 4N), warp 64x32. K chunks of 64 bf16, 3 cp.async stages (32 KB each).
#define STAGE_BYTES 32768
#define SMEM_GEMM_BYTES (3 * STAGE_BYTES)  // 96 KB -> 2 CTAs/SM

template <int RELU, int STATS>
__global__ void __launch_bounds__(256, 2) mma_gemm(
    const __nv_bfloat16* __restrict__ Ahi, const __nv_bfloat16* __restrict__ Alo,
    const __nv_bfloat16* __restrict__ Bhi, const __nv_bfloat16* __restrict__ Blo,
    const float* __restrict__ bias, float* __restrict__ C, int Kd, int Nn) {
    extern __shared__ char smem[];
    uint32_t sb = smem_u32(smem);
    int tid = threadIdx.x, lane = tid & 31, wid = tid >> 5;
    int wm = wid & 1, wn = wid >> 1;
    int row0 = blockIdx.y * 128, col0 = blockIdx.x * 128;
    int KC = Kd >> 6, NIT = 3 * KC;

    float acc[4][4][4];
#pragma unroll
    for (int mi = 0; mi < 4; mi++)
#pragma unroll
        for (int ni = 0; ni < 4; ni++)
#pragma unroll
            for (int j = 0; j < 4; j++) acc[mi][ni][j] = 0.f;

    int lr = tid >> 3, lg = tid & 7;

    auto load_chunk = [&](int idx, int st) {
        int p = idx / KC, kc = idx - p * KC;
        const __nv_bfloat16* As = (p == 1) ? Alo : Ahi;
        const __nv_bfloat16* Bs = (p == 2) ? Blo : Bhi;
        uint32_t abase = sb + st * STAGE_BYTES;
        uint32_t bbase = abase + 16384;
#pragma unroll
        for (int i = 0; i < 4; i++) {
            int r = lr + i * 32;
            CP_ASYNC16(abase + SWZ((uint32_t)(r * 128 + lg * 16)),
                       As + (size_t)(row0 + r) * Kd + kc * 64 + lg * 8);
        }
#pragma unroll
        for (int i = 0; i < 4; i++) {
            int r = lr + i * 32;
            CP_ASYNC16(bbase + SWZ((uint32_t)(r * 128 + lg * 16)),
                       Bs + (size_t)(col0 + r) * Kd + kc * 64 + lg * 8);
        }
        CP_COMMIT();
    };

    load_chunk(0, 0);
    load_chunk(1, 1);

    for (int it = 0; it < NIT; it++) {
        int s = it % 3;
        if (it + 2 < NIT) { load_chunk(it + 2, (it + 2) % 3); CP_WAIT2(); }
        else if (it + 1 < NIT) { CP_WAIT1(); }
        else { CP_WAIT0(); }
        __syncthreads();

        uint32_t abase = sb + s * STAGE_BYTES;
        uint32_t bbase = abase + 16384;
#pragma unroll
        for (int kk = 0; kk < 4; kk++) {
            uint32_t af[4][4];
#pragma unroll
            for (int mi = 0; mi < 4; mi++) {
                int r = wm * 64 + mi * 16 + (lane & 15);
                uint32_t off = (uint32_t)(r * 128 + kk * 32 + (lane >> 4) * 16);
                ldsm_x4(af[mi], abase + SWZ(off));
            }
#pragma unroll
            for (int ni = 0; ni < 4; ni++) {
                uint32_t bfr[2];
                int r = wn * 32 + ni * 8 + (lane & 7);
                uint32_t off = (uint32_t)(r * 128 + kk * 32 + ((lane >> 3) & 1) * 16);
                ldsm_x2(bfr, bbase + SWZ(off));
#pragma unroll
                for (int mi = 0; mi < 4; mi++) mma16816(acc[mi][ni], af[mi], bfr[0], bfr[1]);
            }
        }
        __syncthreads();
    }

    // epilogue: +bias, optional relu, store; optional fused column stats
    float s_[4][2], q_[4][2];
    if (STATS) {
#pragma unroll
        for (int ni = 0; ni < 4; ni++) { s_[ni][0] = s_[ni][1] = q_[ni][0] = q_[ni][1] = 0.f; }
    }
#pragma unroll
    for (int mi = 0; mi < 4; mi++) {
        int row = row0 + wm * 64 + mi * 16 + (lane >> 2);
#pragma unroll
        for (int ni = 0; ni < 4; ni++) {
            int col = col0 + wn * 32 + ni * 8 + (lane & 3) * 2;
            float b0 = bias[col], b1 = bias[col + 1];
            float v0 = acc[mi][ni][0] + b0, v1 = acc[mi][ni][1] + b1;
            float v2 = acc[mi][ni][2] + b0, v3 = acc[mi][ni][3] + b1;
            if (RELU) {
                v0 = fmaxf(v0, 0.f); v1 = fmaxf(v1, 0.f);
                v2 = fmaxf(v2, 0.f); v3 = fmaxf(v3, 0.f);
            }
            if (STATS) {
                s_[ni][0] += v0 + v2; s_[ni][1] += v1 + v3;
                q_[ni][0] += v0 * v0 + v2 * v2; q_[ni][1] += v1 * v1 + v3 * v3;
            }
            *(float2*)(C + (size_t)row * Nn + col) = make_float2(v0, v1);
            *(float2*)(C + (size_t)(row + 8) * Nn + col) = make_float2(v2, v3);
        }
    }
    if (STATS) {
#pragma unroll
        for (int ni = 0; ni < 4; ni++) {
#pragma unroll
            for (int j = 0; j < 2; j++) {
#pragma unroll
                for (int off = 4; off <= 16; off <<= 1) {
                    s_[ni][j] += __shfl_xor_sync(0xffffffffu, s_[ni][j], off);
                    q_[ni][j] += __shfl_xor_sync(0xffffffffu, q_[ni][j], off);
                }
            }
        }
        if ((lane >> 2) == 0) {
#pragma unroll
            for (int ni = 0; ni < 4; ni++) {
                int col = col0 + wn * 32 + ni * 8 + (lane & 3) * 2;
                atomicAdd(&g_sum[col],     s_[ni][0]);
                atomicAdd(&g_sum[col + 1], s_[ni][1]);
                atomicAdd(&g_sumsq[col],     q_[ni][0]);
                atomicAdd(&g_sumsq[col + 1], q_[ni][1]);
            }
        }
    }
}

// ---------------- final tiny GEMM: out[M,5] = h[M,256] @ Wc2[5,256]^T + bc2 -----
__global__ void final_kernel(const float* __restrict__ Wc2, const float* __restrict__ bc2,
                             float* __restrict__ out) {
    __shared__ float w[5 * 256];
    for (int i = threadIdx.x; i < 5 * 256; i += blockDim.x) w[i] = Wc2[i];
    __syncthreads();
    int warp = threadIdx.x >> 5, lane = threadIdx.x & 31;
    int r = blockIdx.x * (blockDim.x >> 5) + warp;
    const float* h = g_h + (size_t)r * 256;
    float a0 = 0, a1 = 0, a2 = 0, a3 = 0, a4 = 0;
    for (int c = lane; c < 256; c += 32) {
        float hv = h[c];
        a0 = fmaf(hv, w[0 * 256 + c], a0);
        a1 = fmaf(hv, w[1 * 256 + c], a1);
        a2 = fmaf(hv, w[2 * 256 + c], a2);
        a3 = fmaf(hv, w[3 * 256 + c], a3);
        a4 = fmaf(hv, w[4 * 256 + c], a4);
    }
#pragma unroll
    for (int off = 16; off; off >>= 1) {
        a0 += __shfl_xor_sync(0xffffffffu, a0, off);
        a1 += __shfl_xor_sync(0xffffffffu, a1, off);
        a2 += __shfl_xor_sync(0xffffffffu, a2, off);
        a3 += __shfl_xor_sync(0xffffffffu, a3, off);
        a4 += __shfl_xor_sync(0xffffffffu, a4, off);
    }
    if (lane == 0) {
        float* o = out + (size_t)r * 5;
        o[0] = a0 + bc2[0];
        o[1] = a1 + bc2[1];
        o[2] = a2 + bc2[2];
        o[3] = a3 + bc2[3];
        o[4] = a4 + bc2[4];
    }
}

// ---------------- launch ----------------
extern "C" void kernel_launch(void* const* d_in, const int* in_sizes, int n_in,
                              void* d_out, int out_size) {
    const float* x    = (const float*)d_in[0];
    const float* pos  = (const float*)d_in[1];
    const float* W[3]  = {(const float*)d_in[2], (const float*)d_in[6], (const float*)d_in[10]};
    const float* bb[3] = {(const float*)d_in[3], (const float*)d_in[7], (const float*)d_in[11]};
    const float* gg[3] = {(const float*)d_in[4], (const float*)d_in[8], (const float*)d_in[12]};
    const float* be[3] = {(const float*)d_in[5], (const float*)d_in[9], (const float*)d_in[13]};
    const float* Wc1 = (const float*)d_in[14];
    const float* bc1 = (const float*)d_in[15];
    const float* Wc2 = (const float*)d_in[16];
    const float* bc2 = (const float*)d_in[17];
    float* out = (float*)d_out;

    float *p_y, *p_h;
    __nv_bfloat16 *p_Ahi, *p_Alo, *p_Xhi, *p_Xlo, *p_Whi, *p_Wlo, *p_Chi, *p_Clo;
    cudaGetSymbolAddress((void**)&p_y, g_y);
    cudaGetSymbolAddress((void**)&p_h, g_h);
    cudaGetSymbolAddress((void**)&p_Ahi, g_Ahi);
    cudaGetSymbolAddress((void**)&p_Alo, g_Alo);
    cudaGetSymbolAddress((void**)&p_Xhi, g_Xhi);
    cudaGetSymbolAddress((void**)&p_Xlo, g_Xlo);
    cudaGetSymbolAddress((void**)&p_Whi, g_Whi);
    cudaGetSymbolAddress((void**)&p_Wlo, g_Wlo);
    cudaGetSymbolAddress((void**)&p_Chi, g_Chi);
    cudaGetSymbolAddress((void**)&p_Clo, g_Clo);

    cudaFuncSetAttribute(mma_gemm<0, 1>, cudaFuncAttributeMaxDynamicSharedMemorySize, SMEM_GEMM_BYTES);
    cudaFuncSetAttribute(mma_gemm<1, 0>, cudaFuncAttributeMaxDynamicSharedMemorySize, SMEM_GEMM_BYTES);

    transpose_kernel<<<dim3(NPTS / 32, CH / 32, BATCH), dim3(32, 8)>>>(x);
    knn_kernel<<<dim3(NPTS / 8, BATCH), 256>>>(pos);
    wsplit_all<<<(3 * W_ELEMS + C_ELEMS) / 256, 256>>>(W[0], W[1], W[2], Wc1);

    for (int i = 0; i < 3; i++) {
        if (i == 0) feat_kernel<<<MROWS, 128>>>();
        else        bnfeat_kernel<<<MROWS, 128>>>();
        zero_stats<<<1, CH>>>();
        mma_gemm<0, 1><<<dim3(CH / 128, MROWS / 128), 256, SMEM_GEMM_BYTES>>>(
            p_Ahi, p_Alo, p_Whi + (size_t)i * CH * KDIM, p_Wlo + (size_t)i * CH * KDIM,
            bb[i], p_y, KDIM, CH);
        bn_coef<<<1, CH>>>(gg[i], be[i]);
    }

    // classifier: Xhi/Xlo = bn+relu(layer3), then h = relu(X @ Wc1^T + bc1)
    bn_apply_cls<<<(MROWS * CH / 4) / 256, 256>>>();
    mma_gemm<1, 0><<<dim3((CH / 2) / 128, MROWS / 128), 256, SMEM_GEMM_BYTES>>>(
        p_Xhi, p_Xlo, p_Chi, p_Clo, bc1, p_h, CH, CH / 2);
    final_kernel<<<MROWS / 8, 256>>>(Wc2, bc2, out);
}

// round 11
// speedup vs baseline: 2.8125x; 1.2947x over previous
#include <cuda_runtime.h>
#include <cuda_fp16.h>
#include <cstdint>

#define BATCH 4
#define CH    512
#define NPTS  4096
#define MROWS (BATCH * NPTS)   // 16384
#define KNN   5
#define KDIM  (2 * CH)         // 1024

// ================= PTX helpers (baseline ISA only — no sm_103a features) =========
__device__ __forceinline__ uint32_t smem_u32(const void* p) {
    return (uint32_t)__cvta_generic_to_shared((void*)p);
}
#define SWZ(o) ((o) ^ (((o) >> 3) & 0x70))

__device__ __forceinline__ void ldsm_x4(uint32_t (&r)[4], uint32_t addr) {
    asm volatile("ldmatrix.sync.aligned.m8n8.x4.shared.b16 {%0,%1,%2,%3}, [%4];"
                 : "=r"(r[0]), "=r"(r[1]), "=r"(r[2]), "=r"(r[3]) : "r"(addr));
}
__device__ __forceinline__ void ldsm_x2(uint32_t (&r)[2], uint32_t addr) {
    asm volatile("ldmatrix.sync.aligned.m8n8.x2.shared.b16 {%0,%1}, [%2];"
                 : "=r"(r[0]), "=r"(r[1]) : "r"(addr));
}
__device__ __forceinline__ void mma16816(float (&c)[4], const uint32_t (&a)[4],
                                         uint32_t b0, uint32_t b1) {
    asm volatile("mma.sync.aligned.m16n8k16.row.col.f32.f16.f16.f32 "
                 "{%0,%1,%2,%3}, {%4,%5,%6,%7}, {%8,%9}, {%0,%1,%2,%3};"
                 : "+f"(c[0]), "+f"(c[1]), "+f"(c[2]), "+f"(c[3])
                 : "r"(a[0]), "r"(a[1]), "r"(a[2]), "r"(a[3]), "r"(b0), "r"(b1));
}
#define CP_ASYNC16(dst, src) \
    asm volatile("cp.async.cg.shared.global [%0], [%1], 16;" :: "r"(dst), "l"(src))
#define CP_COMMIT() asm volatile("cp.async.commit_group;" ::: "memory")
#define CP_WAIT2()  asm volatile("cp.async.wait_group 2;" ::: "memory")
#define CP_WAIT1()  asm volatile("cp.async.wait_group 1;" ::: "memory")
#define CP_WAIT0()  asm volatile("cp.async.wait_group 0;" ::: "memory")

// ================= scratch (static device globals; no allocation) =================
__device__ float g_xt[(size_t)MROWS * CH];
__device__ __align__(16) __half g_Ahi[(size_t)MROWS * KDIM];
__device__ __align__(16) __half g_Alo[(size_t)MROWS * KDIM];
__device__ __align__(16) __half g_Xhi[(size_t)MROWS * CH];
__device__ __align__(16) __half g_Xlo[(size_t)MROWS * CH];
__device__ __align__(16) __half g_Whi[(size_t)3 * CH * KDIM];
__device__ __align__(16) __half g_Chi[(size_t)(CH / 2) * CH];
__device__ float g_y[(size_t)MROWS * CH];
__device__ float g_h[(size_t)MROWS * (CH / 2)];
__device__ int   g_idx[MROWS * KNN];
__device__ float g_sum[CH];
__device__ float g_sumsq[CH];
__device__ __align__(16) float g_bnA[CH];   // rs * gamma
__device__ __align__(16) float g_bnB[CH];   // beta - mean * rs * gamma

__device__ __forceinline__ uint32_t pack_pair(float s, float m, float& sl, float& ml) {
    __half2 v;
    v.x = __float2half_rn(s);
    v.y = __float2half_rn(m);
    sl = s - __half2float(v.x);
    ml = m - __half2float(v.y);
    return *(uint32_t*)&v;
}
__device__ __forceinline__ uint32_t pack_lo(float sl, float ml) {
    __half2 v;
    v.x = __float2half_rn(sl);
    v.y = __float2half_rn(ml);
    return *(uint32_t*)&v;
}

// ---------------- transpose: x [B,C,N] -> g_xt [B*N, C] ----------------
__global__ void transpose_kernel(const float* __restrict__ x) {
    __shared__ float tile[32][33];
    int b = blockIdx.z;
    int n0 = blockIdx.x * 32, c0 = blockIdx.y * 32;
    int tx = threadIdx.x, ty = threadIdx.y;
#pragma unroll
    for (int i = 0; i < 4; i++) {
        int c = c0 + ty + i * 8;
        tile[ty + i * 8][tx] = x[((size_t)(b * CH + c)) * NPTS + n0 + tx];
    }
    __syncthreads();
#pragma unroll
    for (int i = 0; i < 4; i++) {
        int n = n0 + ty + i * 8;
        g_xt[((size_t)(b * NPTS + n)) * CH + c0 + tx] = tile[tx][ty + i * 8];
    }
}

// ---------------- KNN (bit-exact vs reference; DO NOT TOUCH) ----------------
#define LTC(da, ia, db, ib) ((da) < (db) || ((da) == (db) && (ia) < (ib)))

__global__ void knn_kernel(const float* __restrict__ pos) {
    __shared__ float sx[NPTS];
    __shared__ float sy[NPTS];
    __shared__ float sd[NPTS];
    int b = blockIdx.y;
    const float* p = pos + (size_t)b * NPTS * 2;
    for (int j = threadIdx.x; j < NPTS; j += blockDim.x) {
        float xx = p[2 * j], yy = p[2 * j + 1];
        sx[j] = xx; sy[j] = yy;
        sd[j] = __fadd_rn(__fmul_rn(xx, xx), __fmul_rn(yy, yy));  // add-form d2
    }
    __syncthreads();

    int warp = threadIdx.x >> 5, lane = threadIdx.x & 31;
    int q = blockIdx.x * (blockDim.x >> 5) + warp;

    float xi = sx[q], yi = sy[q], d2i = sd[q];
    const float INF = __int_as_float(0x7f800000);
    float d0 = INF, d1 = INF, d2 = INF, d3 = INF, d4 = INF;
    int   i0 = 0x7fffffff, i1 = 0x7fffffff, i2 = 0x7fffffff, i3 = 0x7fffffff, i4 = 0x7fffffff;

    for (int j = lane; j < NPTS; j += 32) {
        float dot  = __fmaf_rn(yi, sy[j], __fmul_rn(xi, sx[j]));  // fma-form dot
        float dist = __fadd_rn(__fadd_rn(d2i, sd[j]), -__fmul_rn(2.0f, dot));
        if (LTC(dist, j, d4, i4)) {
            d4 = dist; i4 = j;
            if (LTC(d4, i4, d3, i3)) { float tf = d3; d3 = d4; d4 = tf; int ti = i3; i3 = i4; i4 = ti; }
            if (LTC(d3, i3, d2, i2)) { float tf = d2; d2 = d3; d3 = tf; int ti = i2; i2 = i3; i3 = ti; }
            if (LTC(d2, i2, d1, i1)) { float tf = d1; d1 = d2; d2 = tf; int ti = i1; i1 = i2; i2 = ti; }
            if (LTC(d1, i1, d0, i0)) { float tf = d0; d0 = d1; d1 = tf; int ti = i0; i0 = i1; i1 = ti; }
        }
    }
#pragma unroll
    for (int k = 0; k < KNN; k++) {
        float od = d0; int oi = i0;
#pragma unroll
        for (int off = 16; off; off >>= 1) {
            float td = __shfl_down_sync(0xffffffffu, od, off);
            int   ti = __shfl_down_sync(0xffffffffu, oi, off);
            if (LTC(td, ti, od, oi)) { od = td; oi = ti; }
        }
        od = __shfl_sync(0xffffffffu, od, 0);
        oi = __shfl_sync(0xffffffffu, oi, 0);
        if (oi == i0) {
            d0 = d1; i0 = i1; d1 = d2; i1 = i2; d2 = d3; i2 = i3; d3 = d4; i3 = i4;
            d4 = INF; i4 = 0x7fffffff;
        }
        if (lane == 0) g_idx[((size_t)(b * NPTS + q)) * KNN + k] = oi;
    }
}

// ---------------- bn coefficient precompute (1 block, 512 threads) ---------------
__global__ void bn_coef(const float* __restrict__ gamma, const float* __restrict__ beta) {
    int c = threadIdx.x;
    const float inv = 1.0f / (float)MROWS;
    float mean = g_sum[c] * inv;
    float var  = g_sumsq[c] * inv - mean * mean;
    float a = rsqrtf(var + 1e-5f) * gamma[c];
    g_bnA[c] = a;
    g_bnB[c] = beta[c] - mean * a;
}

// ---------------- feat (layer 1): gather + maxrel from fp32 g_xt, float4 ---------
__global__ void feat_kernel() {
    __shared__ int nb[KNN];
    int r = blockIdx.x, tid = threadIdx.x;   // 128 threads, c4 = tid
    if (tid < KNN) nb[tid] = (r >> 12) * NPTS + g_idx[r * KNN + tid];
    __syncthreads();
    float4 s = ((const float4*)(g_xt + (size_t)r * CH))[tid];
    float4 m = make_float4(-1e30f, -1e30f, -1e30f, -1e30f);
#pragma unroll
    for (int k = 0; k < KNN; k++) {
        float4 v = ((const float4*)(g_xt + (size_t)nb[k] * CH))[tid];
        m.x = fmaxf(m.x, v.x - s.x); m.y = fmaxf(m.y, v.y - s.y);
        m.z = fmaxf(m.z, v.z - s.z); m.w = fmaxf(m.w, v.w - s.w);
    }
    float slx, mlx, sly, mly, slz, mlz, slw, mlw;
    uint4 hi, lo;
    hi.x = pack_pair(s.x, m.x, slx, mlx);
    hi.y = pack_pair(s.y, m.y, sly, mly);
    hi.z = pack_pair(s.z, m.z, slz, mlz);
    hi.w = pack_pair(s.w, m.w, slw, mlw);
    lo.x = pack_lo(slx, mlx); lo.y = pack_lo(sly, mly);
    lo.z = pack_lo(slz, mlz); lo.w = pack_lo(slw, mlw);
    ((uint4*)(g_Ahi + (size_t)r * KDIM))[tid] = hi;
    ((uint4*)(g_Alo + (size_t)r * KDIM))[tid] = lo;
}

// ---------------- bnfeat (layers 2,3): BN(g_y)+relu on the fly, float4 -----------
__global__ void bnfeat_kernel() {
    __shared__ int nb[KNN];
    int r = blockIdx.x, tid = threadIdx.x;
    if (tid < KNN) nb[tid] = (r >> 12) * NPTS + g_idx[r * KNN + tid];
    __syncthreads();
    float4 a = ((const float4*)g_bnA)[tid];
    float4 b = ((const float4*)g_bnB)[tid];
    float4 y = ((const float4*)(g_y + (size_t)r * CH))[tid];
    float4 s;
    s.x = fmaxf(fmaf(y.x, a.x, b.x), 0.f);
    s.y = fmaxf(fmaf(y.y, a.y, b.y), 0.f);
    s.z = fmaxf(fmaf(y.z, a.z, b.z), 0.f);
    s.w = fmaxf(fmaf(y.w, a.w, b.w), 0.f);
    float4 m = make_float4(-1e30f, -1e30f, -1e30f, -1e30f);
#pragma unroll
    for (int k = 0; k < KNN; k++) {
        float4 v = ((const float4*)(g_y + (size_t)nb[k] * CH))[tid];
        m.x = fmaxf(m.x, fmaxf(fmaf(v.x, a.x, b.x), 0.f) - s.x);
        m.y = fmaxf(m.y, fmaxf(fmaf(v.y, a.y, b.y), 0.f) - s.y);
        m.z = fmaxf(m.z, fmaxf(fmaf(v.z, a.z, b.z), 0.f) - s.z);
        m.w = fmaxf(m.w, fmaxf(fmaf(v.w, a.w, b.w), 0.f) - s.w);
    }
    float slx, mlx, sly, mly, slz, mlz, slw, mlw;
    uint4 hi, lo;
    hi.x = pack_pair(s.x, m.x, slx, mlx);
    hi.y = pack_pair(s.y, m.y, sly, mly);
    hi.z = pack_pair(s.z, m.z, slz, mlz);
    hi.w = pack_pair(s.w, m.w, slw, mlw);
    lo.x = pack_lo(slx, mlx); lo.y = pack_lo(sly, mly);
    lo.z = pack_lo(slz, mlz); lo.w = pack_lo(slw, mlw);
    ((uint4*)(g_Ahi + (size_t)r * KDIM))[tid] = hi;
    ((uint4*)(g_Alo + (size_t)r * KDIM))[tid] = lo;
}

// ---------------- bn_apply for classifier (layer 3 -> Xhi/Xlo), float4 -----------
__global__ void bn_apply_cls() {
    int i4 = blockIdx.x * blockDim.x + threadIdx.x;   // float4 index
    int c4 = i4 & 127;
    float4 a = ((const float4*)g_bnA)[c4];
    float4 b = ((const float4*)g_bnB)[c4];
    float4 y = ((const float4*)g_y)[i4];
    float vx = fmaxf(fmaf(y.x, a.x, b.x), 0.f);
    float vy = fmaxf(fmaf(y.y, a.y, b.y), 0.f);
    float vz = fmaxf(fmaf(y.z, a.z, b.z), 0.f);
    float vw = fmaxf(fmaf(y.w, a.w, b.w), 0.f);
    float l0, l1, l2, l3;
    uint2 hv, lv;
    hv.x = pack_pair(vx, vy, l0, l1);
    hv.y = pack_pair(vz, vw, l2, l3);
    lv.x = pack_lo(l0, l1);
    lv.y = pack_lo(l2, l3);
    ((uint2*)g_Xhi)[i4] = hv;
    ((uint2*)g_Xlo)[i4] = lv;
}

// ---------------- all weight conversions (fp16 hi only) in one launch ------------
#define W_ELEMS (CH * KDIM)
#define C_ELEMS ((CH / 2) * CH)
__global__ void wsplit_all(const float* __restrict__ w1, const float* __restrict__ w2,
                           const float* __restrict__ w3, const float* __restrict__ wc1) {
    int i = blockIdx.x * blockDim.x + threadIdx.x;
    const float* src; __half* hi; int k;
    if (i < W_ELEMS)            { src = w1;  hi = g_Whi;               k = i; }
    else if (i < 2 * W_ELEMS)   { src = w2;  hi = g_Whi + W_ELEMS;     k = i - W_ELEMS; }
    else if (i < 3 * W_ELEMS)   { src = w3;  hi = g_Whi + 2 * W_ELEMS; k = i - 2 * W_ELEMS; }
    else if (i < 3 * W_ELEMS + C_ELEMS) { src = wc1; hi = g_Chi;       k = i - 3 * W_ELEMS; }
    else return;
    hi[k] = __float2half_rn(src[k]);
}

__global__ void zero_stats() {
    g_sum[threadIdx.x] = 0.f;
    g_sumsq[threadIdx.x] = 0.f;
}

// ================= HMMA fp16 2-term GEMM, 128x128 tile, 3-stage, 2 CTA/SM ========
// C[M,Nn] fp32 = Ahi*Bh^T + Alo*Bh^T + bias, optional relu.  (A exact to 2^-22;
// dropped A*Bl is statistical rounding noise ~2e-4/GEMM.)
// 8 warps (2M x 4N), warp 64x32. K chunks of 64 fp16, 3 cp.async stages (32 KB each).
#define STAGE_BYTES 32768
#define SMEM_GEMM_BYTES (3 * STAGE_BYTES)  // 96 KB -> 2 CTAs/SM

template <int RELU, int STATS>
__global__ void __launch_bounds__(256, 2) mma_gemm(
    const __half* __restrict__ Ahi, const __half* __restrict__ Alo,
    const __half* __restrict__ Bh,
    const float* __restrict__ bias, float* __restrict__ C, int Kd, int Nn) {
    extern __shared__ char smem[];
    uint32_t sb = smem_u32(smem);
    int tid = threadIdx.x, lane = tid & 31, wid = tid >> 5;
    int wm = wid & 1, wn = wid >> 1;
    int row0 = blockIdx.y * 128, col0 = blockIdx.x * 128;
    int KC = Kd >> 6, NIT = 2 * KC;

    float acc[4][4][4];
#pragma unroll
    for (int mi = 0; mi < 4; mi++)
#pragma unroll
        for (int ni = 0; ni < 4; ni++)
#pragma unroll
            for (int j = 0; j < 4; j++) acc[mi][ni][j] = 0.f;

    int lr = tid >> 3, lg = tid & 7;

    auto load_chunk = [&](int idx, int st) {
        int p = (idx >= KC);
        int kc = idx - p * KC;
        const __half* As = p ? Alo : Ahi;
        uint32_t abase = sb + st * STAGE_BYTES;
        uint32_t bbase = abase + 16384;
#pragma unroll
        for (int i = 0; i < 4; i++) {
            int r = lr + i * 32;
            CP_ASYNC16(abase + SWZ((uint32_t)(r * 128 + lg * 16)),
                       As + (size_t)(row0 + r) * Kd + kc * 64 + lg * 8);
        }
#pragma unroll
        for (int i = 0; i < 4; i++) {
            int r = lr + i * 32;
            CP_ASYNC16(bbase + SWZ((uint32_t)(r * 128 + lg * 16)),
                       Bh + (size_t)(col0 + r) * Kd + kc * 64 + lg * 8);
        }
        CP_COMMIT();
    };

    load_chunk(0, 0);
    load_chunk(1, 1);

    for (int it = 0; it < NIT; it++) {
        int s = it % 3;
        if (it + 2 < NIT) { load_chunk(it + 2, (it + 2) % 3); CP_WAIT2(); }
        else if (it + 1 < NIT) { CP_WAIT1(); }
        else { CP_WAIT0(); }
        __syncthreads();

        uint32_t abase = sb + s * STAGE_BYTES;
        uint32_t bbase = abase + 16384;
#pragma unroll
        for (int kk = 0; kk < 4; kk++) {
            uint32_t af[4][4];
#pragma unroll
            for (int mi = 0; mi < 4; mi++) {
                int r = wm * 64 + mi * 16 + (lane & 15);
                uint32_t off = (uint32_t)(r * 128 + kk * 32 + (lane >> 4) * 16);
                ldsm_x4(af[mi], abase + SWZ(off));
            }
#pragma unroll
            for (int ni = 0; ni < 4; ni++) {
                uint32_t bfr[2];
                int r = wn * 32 + ni * 8 + (lane & 7);
                uint32_t off = (uint32_t)(r * 128 + kk * 32 + ((lane >> 3) & 1) * 16);
                ldsm_x2(bfr, bbase + SWZ(off));
#pragma unroll
                for (int mi = 0; mi < 4; mi++) mma16816(acc[mi][ni], af[mi], bfr[0], bfr[1]);
            }
        }
        __syncthreads();
    }

    // epilogue: +bias, optional relu, store; optional fused column stats
    float s_[4][2], q_[4][2];
    if (STATS) {
#pragma unroll
        for (int ni = 0; ni < 4; ni++) { s_[ni][0] = s_[ni][1] = q_[ni][0] = q_[ni][1] = 0.f; }
    }
#pragma unroll
    for (int mi = 0; mi < 4; mi++) {
        int row = row0 + wm * 64 + mi * 16 + (lane >> 2);
#pragma unroll
        for (int ni = 0; ni < 4; ni++) {
            int col = col0 + wn * 32 + ni * 8 + (lane & 3) * 2;
            float b0 = bias[col], b1 = bias[col + 1];
            float v0 = acc[mi][ni][0] + b0, v1 = acc[mi][ni][1] + b1;
            float v2 = acc[mi][ni][2] + b0, v3 = acc[mi][ni][3] + b1;
            if (RELU) {
                v0 = fmaxf(v0, 0.f); v1 = fmaxf(v1, 0.f);
                v2 = fmaxf(v2, 0.f); v3 = fmaxf(v3, 0.f);
            }
            if (STATS) {
                s_[ni][0] += v0 + v2; s_[ni][1] += v1 + v3;
                q_[ni][0] += v0 * v0 + v2 * v2; q_[ni][1] += v1 * v1 + v3 * v3;
            }
            *(float2*)(C + (size_t)row * Nn + col) = make_float2(v0, v1);
            *(float2*)(C + (size_t)(row + 8) * Nn + col) = make_float2(v2, v3);
        }
    }
    if (STATS) {
#pragma unroll
        for (int ni = 0; ni < 4; ni++) {
#pragma unroll
            for (int j = 0; j < 2; j++) {
#pragma unroll
                for (int off = 4; off <= 16; off <<= 1) {
                    s_[ni][j] += __shfl_xor_sync(0xffffffffu, s_[ni][j], off);
                    q_[ni][j] += __shfl_xor_sync(0xffffffffu, q_[ni][j], off);
                }
            }
        }
        if ((lane >> 2) == 0) {
#pragma unroll
            for (int ni = 0; ni < 4; ni++) {
                int col = col0 + wn * 32 + ni * 8 + (lane & 3) * 2;
                atomicAdd(&g_sum[col],     s_[ni][0]);
                atomicAdd(&g_sum[col + 1], s_[ni][1]);
                atomicAdd(&g_sumsq[col],     q_[ni][0]);
                atomicAdd(&g_sumsq[col + 1], q_[ni][1]);
            }
        }
    }
}

// ---------------- final tiny GEMM: out[M,5] = h[M,256] @ Wc2[5,256]^T + bc2 -----
__global__ void final_kernel(const float* __restrict__ Wc2, const float* __restrict__ bc2,
                             float* __restrict__ out) {
    __shared__ float w[5 * 256];
    for (int i = threadIdx.x; i < 5 * 256; i += blockDim.x) w[i] = Wc2[i];
    __syncthreads();
    int warp = threadIdx.x >> 5, lane = threadIdx.x & 31;
    int r = blockIdx.x * (blockDim.x >> 5) + warp;
    const float* h = g_h + (size_t)r * 256;
    float a0 = 0, a1 = 0, a2 = 0, a3 = 0, a4 = 0;
    for (int c = lane; c < 256; c += 32) {
        float hv = h[c];
        a0 = fmaf(hv, w[0 * 256 + c], a0);
        a1 = fmaf(hv, w[1 * 256 + c], a1);
        a2 = fmaf(hv, w[2 * 256 + c], a2);
        a3 = fmaf(hv, w[3 * 256 + c], a3);
        a4 = fmaf(hv, w[4 * 256 + c], a4);
    }
#pragma unroll
    for (int off = 16; off; off >>= 1) {
        a0 += __shfl_xor_sync(0xffffffffu, a0, off);
        a1 += __shfl_xor_sync(0xffffffffu, a1, off);
        a2 += __shfl_xor_sync(0xffffffffu, a2, off);
        a3 += __shfl_xor_sync(0xffffffffu, a3, off);
        a4 += __shfl_xor_sync(0xffffffffu, a4, off);
    }
    if (lane == 0) {
        float* o = out + (size_t)r * 5;
        o[0] = a0 + bc2[0];
        o[1] = a1 + bc2[1];
        o[2] = a2 + bc2[2];
        o[3] = a3 + bc2[3];
        o[4] = a4 + bc2[4];
    }
}

// ---------------- launch ----------------
extern "C" void kernel_launch(void* const* d_in, const int* in_sizes, int n_in,
                              void* d_out, int out_size) {
    const float* x    = (const float*)d_in[0];
    const float* pos  = (const float*)d_in[1];
    const float* W[3]  = {(const float*)d_in[2], (const float*)d_in[6], (const float*)d_in[10]};
    const float* bb[3] = {(const float*)d_in[3], (const float*)d_in[7], (const float*)d_in[11]};
    const float* gg[3] = {(const float*)d_in[4], (const float*)d_in[8], (const float*)d_in[12]};
    const float* be[3] = {(const float*)d_in[5], (const float*)d_in[9], (const float*)d_in[13]};
    const float* Wc1 = (const float*)d_in[14];
    const float* bc1 = (const float*)d_in[15];
    const float* Wc2 = (const float*)d_in[16];
    const float* bc2 = (const float*)d_in[17];
    float* out = (float*)d_out;

    float *p_y, *p_h;
    __half *p_Ahi, *p_Alo, *p_Xhi, *p_Xlo, *p_Whi, *p_Chi;
    cudaGetSymbolAddress((void**)&p_y, g_y);
    cudaGetSymbolAddress((void**)&p_h, g_h);
    cudaGetSymbolAddress((void**)&p_Ahi, g_Ahi);
    cudaGetSymbolAddress((void**)&p_Alo, g_Alo);
    cudaGetSymbolAddress((void**)&p_Xhi, g_Xhi);
    cudaGetSymbolAddress((void**)&p_Xlo, g_Xlo);
    cudaGetSymbolAddress((void**)&p_Whi, g_Whi);
    cudaGetSymbolAddress((void**)&p_Chi, g_Chi);

    cudaFuncSetAttribute(mma_gemm<0, 1>, cudaFuncAttributeMaxDynamicSharedMemorySize, SMEM_GEMM_BYTES);
    cudaFuncSetAttribute(mma_gemm<1, 0>, cudaFuncAttributeMaxDynamicSharedMemorySize, SMEM_GEMM_BYTES);

    transpose_kernel<<<dim3(NPTS / 32, CH / 32, BATCH), dim3(32, 8)>>>(x);
    knn_kernel<<<dim3(NPTS / 8, BATCH), 256>>>(pos);
    wsplit_all<<<(3 * W_ELEMS + C_ELEMS) / 256, 256>>>(W[0], W[1], W[2], Wc1);

    for (int i = 0; i < 3; i++) {
        if (i == 0) feat_kernel<<<MROWS, 128>>>();
        else        bnfeat_kernel<<<MROWS, 128>>>();
        zero_stats<<<1, CH>>>();
        mma_gemm<0, 1><<<dim3(CH / 128, MROWS / 128), 256, SMEM_GEMM_BYTES>>>(
            p_Ahi, p_Alo, p_Whi + (size_t)i * CH * KDIM,
            bb[i], p_y, KDIM, CH);
        bn_coef<<<1, CH>>>(gg[i], be[i]);
    }

    // classifier: Xhi/Xlo = bn+relu(layer3), then h = relu(X @ Wc1^T + bc1)
    bn_apply_cls<<<(MROWS * CH / 4) / 256, 256>>>();
    mma_gemm<1, 0><<<dim3((CH / 2) / 128, MROWS / 128), 256, SMEM_GEMM_BYTES>>>(
        p_Xhi, p_Xlo, p_Chi, bc1, p_h, CH, CH / 2);
    final_kernel<<<MROWS / 8, 256>>>(Wc2, bc2, out);
}

// round 12
// speedup vs baseline: 2.8618x; 1.0175x over previous
#include <cuda_runtime.h>
#include <cuda_fp16.h>
#include <cstdint>

#define BATCH 4
#define CH    512
#define NPTS  4096
#define MROWS (BATCH * NPTS)   // 16384
#define KNN   5
#define KDIM  (2 * CH)         // 1024

// ================= PTX helpers (baseline ISA only — no sm_103a features) =========
__device__ __forceinline__ uint32_t smem_u32(const void* p) {
    return (uint32_t)__cvta_generic_to_shared((void*)p);
}
#define SWZ(o) ((o) ^ (((o) >> 3) & 0x70))

__device__ __forceinline__ void ldsm_x4(uint32_t (&r)[4], uint32_t addr) {
    asm volatile("ldmatrix.sync.aligned.m8n8.x4.shared.b16 {%0,%1,%2,%3}, [%4];"
                 : "=r"(r[0]), "=r"(r[1]), "=r"(r[2]), "=r"(r[3]) : "r"(addr));
}
__device__ __forceinline__ void ldsm_x2(uint32_t (&r)[2], uint32_t addr) {
    asm volatile("ldmatrix.sync.aligned.m8n8.x2.shared.b16 {%0,%1}, [%2];"
                 : "=r"(r[0]), "=r"(r[1]) : "r"(addr));
}
__device__ __forceinline__ void mma16816(float (&c)[4], const uint32_t (&a)[4],
                                         uint32_t b0, uint32_t b1) {
    asm volatile("mma.sync.aligned.m16n8k16.row.col.f32.f16.f16.f32 "
                 "{%0,%1,%2,%3}, {%4,%5,%6,%7}, {%8,%9}, {%0,%1,%2,%3};"
                 : "+f"(c[0]), "+f"(c[1]), "+f"(c[2]), "+f"(c[3])
                 : "r"(a[0]), "r"(a[1]), "r"(a[2]), "r"(a[3]), "r"(b0), "r"(b1));
}
#define CP_ASYNC16(dst, src) \
    asm volatile("cp.async.cg.shared.global [%0], [%1], 16;" :: "r"(dst), "l"(src))
#define CP_COMMIT() asm volatile("cp.async.commit_group;" ::: "memory")
#define CP_WAIT2()  asm volatile("cp.async.wait_group 2;" ::: "memory")
#define CP_WAIT1()  asm volatile("cp.async.wait_group 1;" ::: "memory")
#define CP_WAIT0()  asm volatile("cp.async.wait_group 0;" ::: "memory")

// ================= scratch (static device globals; no allocation) =================
__device__ float g_xt[(size_t)MROWS * CH];
__device__ __align__(16) __half g_Ahi[(size_t)MROWS * KDIM];
__device__ __align__(16) __half g_Alo[(size_t)MROWS * KDIM];
__device__ __align__(16) __half g_Xhi[(size_t)MROWS * CH];
__device__ __align__(16) __half g_Whi[(size_t)3 * CH * KDIM];
__device__ __align__(16) __half g_Chi[(size_t)(CH / 2) * CH];
__device__ float g_y[(size_t)MROWS * CH];
__device__ float g_h[(size_t)MROWS * (CH / 2)];
__device__ int   g_idx[MROWS * KNN];
__device__ float g_sum[CH];
__device__ float g_sumsq[CH];
__device__ __align__(16) float g_bnA[CH];   // rs * gamma
__device__ __align__(16) float g_bnB[CH];   // beta - mean * rs * gamma

__device__ __forceinline__ uint32_t pack_pair(float s, float m, float& sl, float& ml) {
    __half2 v;
    v.x = __float2half_rn(s);
    v.y = __float2half_rn(m);
    sl = s - __half2float(v.x);
    ml = m - __half2float(v.y);
    return *(uint32_t*)&v;
}
__device__ __forceinline__ uint32_t pack_lo(float sl, float ml) {
    __half2 v;
    v.x = __float2half_rn(sl);
    v.y = __float2half_rn(ml);
    return *(uint32_t*)&v;
}

// ---------------- transpose: x [B,C,N] -> g_xt [B*N, C] ----------------
__global__ void transpose_kernel(const float* __restrict__ x) {
    __shared__ float tile[32][33];
    int b = blockIdx.z;
    int n0 = blockIdx.x * 32, c0 = blockIdx.y * 32;
    int tx = threadIdx.x, ty = threadIdx.y;
#pragma unroll
    for (int i = 0; i < 4; i++) {
        int c = c0 + ty + i * 8;
        tile[ty + i * 8][tx] = x[((size_t)(b * CH + c)) * NPTS + n0 + tx];
    }
    __syncthreads();
#pragma unroll
    for (int i = 0; i < 4; i++) {
        int n = n0 + ty + i * 8;
        g_xt[((size_t)(b * NPTS + n)) * CH + c0 + tx] = tile[tx][ty + i * 8];
    }
}

// ---------------- KNN (bit-exact vs reference; DO NOT TOUCH) ----------------
#define LTC(da, ia, db, ib) ((da) < (db) || ((da) == (db) && (ia) < (ib)))

__global__ void knn_kernel(const float* __restrict__ pos) {
    __shared__ float sx[NPTS];
    __shared__ float sy[NPTS];
    __shared__ float sd[NPTS];
    int b = blockIdx.y;
    const float* p = pos + (size_t)b * NPTS * 2;
    for (int j = threadIdx.x; j < NPTS; j += blockDim.x) {
        float xx = p[2 * j], yy = p[2 * j + 1];
        sx[j] = xx; sy[j] = yy;
        sd[j] = __fadd_rn(__fmul_rn(xx, xx), __fmul_rn(yy, yy));  // add-form d2
    }
    __syncthreads();

    int warp = threadIdx.x >> 5, lane = threadIdx.x & 31;
    int q = blockIdx.x * (blockDim.x >> 5) + warp;

    float xi = sx[q], yi = sy[q], d2i = sd[q];
    const float INF = __int_as_float(0x7f800000);
    float d0 = INF, d1 = INF, d2 = INF, d3 = INF, d4 = INF;
    int   i0 = 0x7fffffff, i1 = 0x7fffffff, i2 = 0x7fffffff, i3 = 0x7fffffff, i4 = 0x7fffffff;

    for (int j = lane; j < NPTS; j += 32) {
        float dot  = __fmaf_rn(yi, sy[j], __fmul_rn(xi, sx[j]));  // fma-form dot
        float dist = __fadd_rn(__fadd_rn(d2i, sd[j]), -__fmul_rn(2.0f, dot));
        if (LTC(dist, j, d4, i4)) {
            d4 = dist; i4 = j;
            if (LTC(d4, i4, d3, i3)) { float tf = d3; d3 = d4; d4 = tf; int ti = i3; i3 = i4; i4 = ti; }
            if (LTC(d3, i3, d2, i2)) { float tf = d2; d2 = d3; d3 = tf; int ti = i2; i2 = i3; i3 = ti; }
            if (LTC(d2, i2, d1, i1)) { float tf = d1; d1 = d2; d2 = tf; int ti = i1; i1 = i2; i2 = ti; }
            if (LTC(d1, i1, d0, i0)) { float tf = d0; d0 = d1; d1 = tf; int ti = i0; i0 = i1; i1 = ti; }
        }
    }
#pragma unroll
    for (int k = 0; k < KNN; k++) {
        float od = d0; int oi = i0;
#pragma unroll
        for (int off = 16; off; off >>= 1) {
            float td = __shfl_down_sync(0xffffffffu, od, off);
            int   ti = __shfl_down_sync(0xffffffffu, oi, off);
            if (LTC(td, ti, od, oi)) { od = td; oi = ti; }
        }
        od = __shfl_sync(0xffffffffu, od, 0);
        oi = __shfl_sync(0xffffffffu, oi, 0);
        if (oi == i0) {
            d0 = d1; i0 = i1; d1 = d2; i1 = i2; d2 = d3; i2 = i3; d3 = d4; i3 = i4;
            d4 = INF; i4 = 0x7fffffff;
        }
        if (lane == 0) g_idx[((size_t)(b * NPTS + q)) * KNN + k] = oi;
    }
}

// ---------------- bn coefficients + stats reset (1 block, 512 threads) -----------
__global__ void bn_coef(const float* __restrict__ gamma, const float* __restrict__ beta) {
    int c = threadIdx.x;
    const float inv = 1.0f / (float)MROWS;
    float mean = g_sum[c] * inv;
    float var  = g_sumsq[c] * inv - mean * mean;
    float a = rsqrtf(var + 1e-5f) * gamma[c];
    g_bnA[c] = a;
    g_bnB[c] = beta[c] - mean * a;
    g_sum[c] = 0.f;       // re-zero for the next GEMM's fused stats
    g_sumsq[c] = 0.f;
}

// ---------------- feat (layer 1): 2 rows per block (256 thr), float4 -------------
__global__ void feat_kernel() {
    __shared__ int nb[2][KNN];
    int tid = threadIdx.x;
    int half = tid >> 7, t = tid & 127;
    int r = blockIdx.x * 2 + half;
    if (t < KNN) nb[half][t] = (r >> 12) * NPTS + g_idx[r * KNN + t];
    __syncthreads();
    float4 s = ((const float4*)(g_xt + (size_t)r * CH))[t];
    float4 m = make_float4(-1e30f, -1e30f, -1e30f, -1e30f);
#pragma unroll
    for (int k = 0; k < KNN; k++) {
        float4 v = ((const float4*)(g_xt + (size_t)nb[half][k] * CH))[t];
        m.x = fmaxf(m.x, v.x - s.x); m.y = fmaxf(m.y, v.y - s.y);
        m.z = fmaxf(m.z, v.z - s.z); m.w = fmaxf(m.w, v.w - s.w);
    }
    float slx, mlx, sly, mly, slz, mlz, slw, mlw;
    uint4 hi, lo;
    hi.x = pack_pair(s.x, m.x, slx, mlx);
    hi.y = pack_pair(s.y, m.y, sly, mly);
    hi.z = pack_pair(s.z, m.z, slz, mlz);
    hi.w = pack_pair(s.w, m.w, slw, mlw);
    lo.x = pack_lo(slx, mlx); lo.y = pack_lo(sly, mly);
    lo.z = pack_lo(slz, mlz); lo.w = pack_lo(slw, mlw);
    ((uint4*)(g_Ahi + (size_t)r * KDIM))[t] = hi;
    ((uint4*)(g_Alo + (size_t)r * KDIM))[t] = lo;
}

// ---------------- bnfeat (layers 2,3): 2 rows per block (256 thr), float4 --------
__global__ void bnfeat_kernel() {
    __shared__ int nb[2][KNN];
    int tid = threadIdx.x;
    int half = tid >> 7, t = tid & 127;
    int r = blockIdx.x * 2 + half;
    if (t < KNN) nb[half][t] = (r >> 12) * NPTS + g_idx[r * KNN + t];
    __syncthreads();
    float4 a = ((const float4*)g_bnA)[t];
    float4 b = ((const float4*)g_bnB)[t];
    float4 y = ((const float4*)(g_y + (size_t)r * CH))[t];
    float4 s;
    s.x = fmaxf(fmaf(y.x, a.x, b.x), 0.f);
    s.y = fmaxf(fmaf(y.y, a.y, b.y), 0.f);
    s.z = fmaxf(fmaf(y.z, a.z, b.z), 0.f);
    s.w = fmaxf(fmaf(y.w, a.w, b.w), 0.f);
    float4 m = make_float4(-1e30f, -1e30f, -1e30f, -1e30f);
#pragma unroll
    for (int k = 0; k < KNN; k++) {
        float4 v = ((const float4*)(g_y + (size_t)nb[half][k] * CH))[t];
        m.x = fmaxf(m.x, fmaxf(fmaf(v.x, a.x, b.x), 0.f) - s.x);
        m.y = fmaxf(m.y, fmaxf(fmaf(v.y, a.y, b.y), 0.f) - s.y);
        m.z = fmaxf(m.z, fmaxf(fmaf(v.z, a.z, b.z), 0.f) - s.z);
        m.w = fmaxf(m.w, fmaxf(fmaf(v.w, a.w, b.w), 0.f) - s.w);
    }
    float slx, mlx, sly, mly, slz, mlz, slw, mlw;
    uint4 hi, lo;
    hi.x = pack_pair(s.x, m.x, slx, mlx);
    hi.y = pack_pair(s.y, m.y, sly, mly);
    hi.z = pack_pair(s.z, m.z, slz, mlz);
    hi.w = pack_pair(s.w, m.w, slw, mlw);
    lo.x = pack_lo(slx, mlx); lo.y = pack_lo(sly, mly);
    lo.z = pack_lo(slz, mlz); lo.w = pack_lo(slw, mlw);
    ((uint4*)(g_Ahi + (size_t)r * KDIM))[t] = hi;
    ((uint4*)(g_Alo + (size_t)r * KDIM))[t] = lo;
}

// ---------------- bn_apply for classifier (layer 3 -> Xhi only), float4 ----------
__global__ void bn_apply_cls() {
    int i4 = blockIdx.x * blockDim.x + threadIdx.x;   // float4 index
    int c4 = i4 & 127;
    float4 a = ((const float4*)g_bnA)[c4];
    float4 b = ((const float4*)g_bnB)[c4];
    float4 y = ((const float4*)g_y)[i4];
    float vx = fmaxf(fmaf(y.x, a.x, b.x), 0.f);
    float vy = fmaxf(fmaf(y.y, a.y, b.y), 0.f);
    float vz = fmaxf(fmaf(y.z, a.z, b.z), 0.f);
    float vw = fmaxf(fmaf(y.w, a.w, b.w), 0.f);
    __half2 h0; h0.x = __float2half_rn(vx); h0.y = __float2half_rn(vy);
    __half2 h1; h1.x = __float2half_rn(vz); h1.y = __float2half_rn(vw);
    uint2 hv = make_uint2(*(uint32_t*)&h0, *(uint32_t*)&h1);
    ((uint2*)g_Xhi)[i4] = hv;
}

// ---------------- all weight conversions (fp16 hi only) + initial stats zero -----
#define W_ELEMS (CH * KDIM)
#define C_ELEMS ((CH / 2) * CH)
__global__ void wsplit_all(const float* __restrict__ w1, const float* __restrict__ w2,
                           const float* __restrict__ w3, const float* __restrict__ wc1) {
    int i = blockIdx.x * blockDim.x + threadIdx.x;
    if (i < CH) { g_sum[i] = 0.f; g_sumsq[i] = 0.f; }
    const float* src; __half* hi; int k;
    if (i < W_ELEMS)            { src = w1;  hi = g_Whi;               k = i; }
    else if (i < 2 * W_ELEMS)   { src = w2;  hi = g_Whi + W_ELEMS;     k = i - W_ELEMS; }
    else if (i < 3 * W_ELEMS)   { src = w3;  hi = g_Whi + 2 * W_ELEMS; k = i - 2 * W_ELEMS; }
    else if (i < 3 * W_ELEMS + C_ELEMS) { src = wc1; hi = g_Chi;       k = i - 3 * W_ELEMS; }
    else return;
    hi[k] = __float2half_rn(src[k]);
}

// ================= HMMA fp16 GEMM, 128x128 tile, 3-stage, 2 CTA/SM ===============
// TERMS=2: C = Ahi*Bh^T + Alo*Bh^T + bias.  TERMS=1: C = Ahi*Bh^T + bias.
// 8 warps (2M x 4N), warp 64x32. K chunks of 64 fp16, 3 cp.async stages (32 KB each).
#define STAGE_BYTES 32768
#define SMEM_GEMM_BYTES (3 * STAGE_BYTES)  // 96 KB -> 2 CTAs/SM

template <int RELU, int STATS, int TERMS>
__global__ void __launch_bounds__(256, 2) mma_gemm(
    const __half* __restrict__ Ahi, const __half* __restrict__ Alo,
    const __half* __restrict__ Bh,
    const float* __restrict__ bias, float* __restrict__ C, int Kd, int Nn) {
    extern __shared__ char smem[];
    uint32_t sb = smem_u32(smem);
    int tid = threadIdx.x, lane = tid & 31, wid = tid >> 5;
    int wm = wid & 1, wn = wid >> 1;
    int row0 = blockIdx.y * 128, col0 = blockIdx.x * 128;
    int KC = Kd >> 6, NIT = TERMS * KC;

    float acc[4][4][4];
#pragma unroll
    for (int mi = 0; mi < 4; mi++)
#pragma unroll
        for (int ni = 0; ni < 4; ni++)
#pragma unroll
            for (int j = 0; j < 4; j++) acc[mi][ni][j] = 0.f;

    int lr = tid >> 3, lg = tid & 7;

    auto load_chunk = [&](int idx, int st) {
        int p = (idx >= KC);
        int kc = idx - p * KC;
        const __half* As = p ? Alo : Ahi;
        uint32_t abase = sb + st * STAGE_BYTES;
        uint32_t bbase = abase + 16384;
#pragma unroll
        for (int i = 0; i < 4; i++) {
            int r = lr + i * 32;
            CP_ASYNC16(abase + SWZ((uint32_t)(r * 128 + lg * 16)),
                       As + (size_t)(row0 + r) * Kd + kc * 64 + lg * 8);
        }
#pragma unroll
        for (int i = 0; i < 4; i++) {
            int r = lr + i * 32;
            CP_ASYNC16(bbase + SWZ((uint32_t)(r * 128 + lg * 16)),
                       Bh + (size_t)(col0 + r) * Kd + kc * 64 + lg * 8);
        }
        CP_COMMIT();
    };

    load_chunk(0, 0);
    load_chunk(1, 1);

    for (int it = 0; it < NIT; it++) {
        int s = it % 3;
        if (it + 2 < NIT) { load_chunk(it + 2, (it + 2) % 3); CP_WAIT2(); }
        else if (it + 1 < NIT) { CP_WAIT1(); }
        else { CP_WAIT0(); }
        __syncthreads();

        uint32_t abase = sb + s * STAGE_BYTES;
        uint32_t bbase = abase + 16384;
#pragma unroll
        for (int kk = 0; kk < 4; kk++) {
            uint32_t af[4][4];
#pragma unroll
            for (int mi = 0; mi < 4; mi++) {
                int r = wm * 64 + mi * 16 + (lane & 15);
                uint32_t off = (uint32_t)(r * 128 + kk * 32 + (lane >> 4) * 16);
                ldsm_x4(af[mi], abase + SWZ(off));
            }
#pragma unroll
            for (int ni = 0; ni < 4; ni++) {
                uint32_t bfr[2];
                int r = wn * 32 + ni * 8 + (lane & 7);
                uint32_t off = (uint32_t)(r * 128 + kk * 32 + ((lane >> 3) & 1) * 16);
                ldsm_x2(bfr, bbase + SWZ(off));
#pragma unroll
                for (int mi = 0; mi < 4; mi++) mma16816(acc[mi][ni], af[mi], bfr[0], bfr[1]);
            }
        }
        __syncthreads();
    }

    // epilogue: +bias, optional relu, store; optional fused column stats
    float s_[4][2], q_[4][2];
    if (STATS) {
#pragma unroll
        for (int ni = 0; ni < 4; ni++) { s_[ni][0] = s_[ni][1] = q_[ni][0] = q_[ni][1] = 0.f; }
    }
#pragma unroll
    for (int mi = 0; mi < 4; mi++) {
        int row = row0 + wm * 64 + mi * 16 + (lane >> 2);
#pragma unroll
        for (int ni = 0; ni < 4; ni++) {
            int col = col0 + wn * 32 + ni * 8 + (lane & 3) * 2;
            float b0 = bias[col], b1 = bias[col + 1];
            float v0 = acc[mi][ni][0] + b0, v1 = acc[mi][ni][1] + b1;
            float v2 = acc[mi][ni][2] + b0, v3 = acc[mi][ni][3] + b1;
            if (RELU) {
                v0 = fmaxf(v0, 0.f); v1 = fmaxf(v1, 0.f);
                v2 = fmaxf(v2, 0.f); v3 = fmaxf(v3, 0.f);
            }
            if (STATS) {
                s_[ni][0] += v0 + v2; s_[ni][1] += v1 + v3;
                q_[ni][0] += v0 * v0 + v2 * v2; q_[ni][1] += v1 * v1 + v3 * v3;
            }
            *(float2*)(C + (size_t)row * Nn + col) = make_float2(v0, v1);
            *(float2*)(C + (size_t)(row + 8) * Nn + col) = make_float2(v2, v3);
        }
    }
    if (STATS) {
#pragma unroll
        for (int ni = 0; ni < 4; ni++) {
#pragma unroll
            for (int j = 0; j < 2; j++) {
#pragma unroll
                for (int off = 4; off <= 16; off <<= 1) {
                    s_[ni][j] += __shfl_xor_sync(0xffffffffu, s_[ni][j], off);
                    q_[ni][j] += __shfl_xor_sync(0xffffffffu, q_[ni][j], off);
                }
            }
        }
        if ((lane >> 2) == 0) {
#pragma unroll
            for (int ni = 0; ni < 4; ni++) {
                int col = col0 + wn * 32 + ni * 8 + (lane & 3) * 2;
                atomicAdd(&g_sum[col],     s_[ni][0]);
                atomicAdd(&g_sum[col + 1], s_[ni][1]);
                atomicAdd(&g_sumsq[col],     q_[ni][0]);
                atomicAdd(&g_sumsq[col + 1], q_[ni][1]);
            }
        }
    }
}

// ---------------- final tiny GEMM: out[M,5] = h[M,256] @ Wc2[5,256]^T + bc2 -----
__global__ void final_kernel(const float* __restrict__ Wc2, const float* __restrict__ bc2,
                             float* __restrict__ out) {
    __shared__ float w[5 * 256];
    for (int i = threadIdx.x; i < 5 * 256; i += blockDim.x) w[i] = Wc2[i];
    __syncthreads();
    int warp = threadIdx.x >> 5, lane = threadIdx.x & 31;
    int r = blockIdx.x * (blockDim.x >> 5) + warp;
    const float* h = g_h + (size_t)r * 256;
    float a0 = 0, a1 = 0, a2 = 0, a3 = 0, a4 = 0;
    for (int c = lane; c < 256; c += 32) {
        float hv = h[c];
        a0 = fmaf(hv, w[0 * 256 + c], a0);
        a1 = fmaf(hv, w[1 * 256 + c], a1);
        a2 = fmaf(hv, w[2 * 256 + c], a2);
        a3 = fmaf(hv, w[3 * 256 + c], a3);
        a4 = fmaf(hv, w[4 * 256 + c], a4);
    }
#pragma unroll
    for (int off = 16; off; off >>= 1) {
        a0 += __shfl_xor_sync(0xffffffffu, a0, off);
        a1 += __shfl_xor_sync(0xffffffffu, a1, off);
        a2 += __shfl_xor_sync(0xffffffffu, a2, off);
        a3 += __shfl_xor_sync(0xffffffffu, a3, off);
        a4 += __shfl_xor_sync(0xffffffffu, a4, off);
    }
    if (lane == 0) {
        float* o = out + (size_t)r * 5;
        o[0] = a0 + bc2[0];
        o[1] = a1 + bc2[1];
        o[2] = a2 + bc2[2];
        o[3] = a3 + bc2[3];
        o[4] = a4 + bc2[4];
    }
}

// ---------------- launch ----------------
extern "C" void kernel_launch(void* const* d_in, const int* in_sizes, int n_in,
                              void* d_out, int out_size) {
    const float* x    = (const float*)d_in[0];
    const float* pos  = (const float*)d_in[1];
    const float* W[3]  = {(const float*)d_in[2], (const float*)d_in[6], (const float*)d_in[10]};
    const float* bb[3] = {(const float*)d_in[3], (const float*)d_in[7], (const float*)d_in[11]};
    const float* gg[3] = {(const float*)d_in[4], (const float*)d_in[8], (const float*)d_in[12]};
    const float* be[3] = {(const float*)d_in[5], (const float*)d_in[9], (const float*)d_in[13]};
    const float* Wc1 = (const float*)d_in[14];
    const float* bc1 = (const float*)d_in[15];
    const float* Wc2 = (const float*)d_in[16];
    const float* bc2 = (const float*)d_in[17];
    float* out = (float*)d_out;

    float *p_y, *p_h;
    __half *p_Ahi, *p_Alo, *p_Xhi, *p_Whi, *p_Chi;
    cudaGetSymbolAddress((void**)&p_y, g_y);
    cudaGetSymbolAddress((void**)&p_h, g_h);
    cudaGetSymbolAddress((void**)&p_Ahi, g_Ahi);
    cudaGetSymbolAddress((void**)&p_Alo, g_Alo);
    cudaGetSymbolAddress((void**)&p_Xhi, g_Xhi);
    cudaGetSymbolAddress((void**)&p_Whi, g_Whi);
    cudaGetSymbolAddress((void**)&p_Chi, g_Chi);

    cudaFuncSetAttribute(mma_gemm<0, 1, 2>, cudaFuncAttributeMaxDynamicSharedMemorySize, SMEM_GEMM_BYTES);
    cudaFuncSetAttribute(mma_gemm<1, 0, 1>, cudaFuncAttributeMaxDynamicSharedMemorySize, SMEM_GEMM_BYTES);

    transpose_kernel<<<dim3(NPTS / 32, CH / 32, BATCH), dim3(32, 8)>>>(x);
    knn_kernel<<<dim3(NPTS / 8, BATCH), 256>>>(pos);
    wsplit_all<<<(3 * W_ELEMS + C_ELEMS) / 256, 256>>>(W[0], W[1], W[2], Wc1);

    for (int i = 0; i < 3; i++) {
        if (i == 0) feat_kernel<<<MROWS / 2, 256>>>();
        else        bnfeat_kernel<<<MROWS / 2, 256>>>();
        mma_gemm<0, 1, 2><<<dim3(CH / 128, MROWS / 128), 256, SMEM_GEMM_BYTES>>>(
            p_Ahi, p_Alo, p_Whi + (size_t)i * CH * KDIM,
            bb[i], p_y, KDIM, CH);
        bn_coef<<<1, CH>>>(gg[i], be[i]);
    }

    // classifier: Xhi = bn+relu(layer3), then h = relu(X @ Wc1^T + bc1) (1-term)
    bn_apply_cls<<<(MROWS * CH / 4) / 256, 256>>>();
    mma_gemm<1, 0, 1><<<dim3((CH / 2) / 128, MROWS / 128), 256, SMEM_GEMM_BYTES>>>(
        p_Xhi, p_Xhi, p_Chi, bc1, p_h, CH, CH / 2);
    final_kernel<<<MROWS / 8, 256>>>(Wc2, bc2, out);
}

// round 13
// speedup vs baseline: 3.1601x; 1.1042x over previous
#include <cuda_runtime.h>
#include <cuda_fp16.h>
#include <cstdint>

#define BATCH 4
#define CH    512
#define NPTS  4096
#define MROWS (BATCH * NPTS)   // 16384
#define KNN   5
#define KDIM  (2 * CH)         // 1024

// ================= PTX helpers (baseline ISA only — no sm_103a features) =========
__device__ __forceinline__ uint32_t smem_u32(const void* p) {
    return (uint32_t)__cvta_generic_to_shared((void*)p);
}
#define SWZ(o) ((o) ^ (((o) >> 3) & 0x70))

__device__ __forceinline__ void ldsm_x4(uint32_t (&r)[4], uint32_t addr) {
    asm volatile("ldmatrix.sync.aligned.m8n8.x4.shared.b16 {%0,%1,%2,%3}, [%4];"
                 : "=r"(r[0]), "=r"(r[1]), "=r"(r[2]), "=r"(r[3]) : "r"(addr));
}
__device__ __forceinline__ void ldsm_x2(uint32_t (&r)[2], uint32_t addr) {
    asm volatile("ldmatrix.sync.aligned.m8n8.x2.shared.b16 {%0,%1}, [%2];"
                 : "=r"(r[0]), "=r"(r[1]) : "r"(addr));
}
__device__ __forceinline__ void mma16816(float (&c)[4], const uint32_t (&a)[4],
                                         uint32_t b0, uint32_t b1) {
    asm volatile("mma.sync.aligned.m16n8k16.row.col.f32.f16.f16.f32 "
                 "{%0,%1,%2,%3}, {%4,%5,%6,%7}, {%8,%9}, {%0,%1,%2,%3};"
                 : "+f"(c[0]), "+f"(c[1]), "+f"(c[2]), "+f"(c[3])
                 : "r"(a[0]), "r"(a[1]), "r"(a[2]), "r"(a[3]), "r"(b0), "r"(b1));
}
#define CP_ASYNC16(dst, src) \
    asm volatile("cp.async.cg.shared.global [%0], [%1], 16;" :: "r"(dst), "l"(src))
#define CP_COMMIT() asm volatile("cp.async.commit_group;" ::: "memory")
#define CP_WAIT1()  asm volatile("cp.async.wait_group 1;" ::: "memory")
#define CP_WAIT0()  asm volatile("cp.async.wait_group 0;" ::: "memory")

// ================= scratch (static device globals; no allocation) =================
__device__ float g_xt[(size_t)MROWS * CH];
__device__ __align__(16) __half g_Ahi[(size_t)MROWS * KDIM];
__device__ __align__(16) __half g_Alo[(size_t)MROWS * KDIM];
__device__ __align__(16) __half g_Xhi[(size_t)MROWS * CH];
__device__ __align__(16) __half g_Whi[(size_t)3 * CH * KDIM];
__device__ __align__(16) __half g_Chi[(size_t)(CH / 2) * CH];
__device__ float g_y[(size_t)MROWS * CH];
__device__ float g_h[(size_t)MROWS * (CH / 2)];
__device__ int   g_idx[MROWS * KNN];
__device__ float g_sum[CH];
__device__ float g_sumsq[CH];
__device__ __align__(16) float g_bnA[CH];   // rs * gamma
__device__ __align__(16) float g_bnB[CH];   // beta - mean * rs * gamma

__device__ __forceinline__ uint32_t pack_pair(float s, float m, float& sl, float& ml) {
    __half2 v;
    v.x = __float2half_rn(s);
    v.y = __float2half_rn(m);
    sl = s - __half2float(v.x);
    ml = m - __half2float(v.y);
    return *(uint32_t*)&v;
}
__device__ __forceinline__ uint32_t pack_lo(float sl, float ml) {
    __half2 v;
    v.x = __float2half_rn(sl);
    v.y = __float2half_rn(ml);
    return *(uint32_t*)&v;
}

// ---------------- transpose: x [B,C,N] -> g_xt [B*N, C] ----------------
__global__ void transpose_kernel(const float* __restrict__ x) {
    __shared__ float tile[32][33];
    int b = blockIdx.z;
    int n0 = blockIdx.x * 32, c0 = blockIdx.y * 32;
    int tx = threadIdx.x, ty = threadIdx.y;
#pragma unroll
    for (int i = 0; i < 4; i++) {
        int c = c0 + ty + i * 8;
        tile[ty + i * 8][tx] = x[((size_t)(b * CH + c)) * NPTS + n0 + tx];
    }
    __syncthreads();
#pragma unroll
    for (int i = 0; i < 4; i++) {
        int n = n0 + ty + i * 8;
        g_xt[((size_t)(b * NPTS + n)) * CH + c0 + tx] = tile[tx][ty + i * 8];
    }
}

// ---------------- KNN (bit-exact vs reference; DO NOT TOUCH) ----------------
#define LTC(da, ia, db, ib) ((da) < (db) || ((da) == (db) && (ia) < (ib)))

__global__ void knn_kernel(const float* __restrict__ pos) {
    __shared__ float sx[NPTS];
    __shared__ float sy[NPTS];
    __shared__ float sd[NPTS];
    int b = blockIdx.y;
    const float* p = pos + (size_t)b * NPTS * 2;
    for (int j = threadIdx.x; j < NPTS; j += blockDim.x) {
        float xx = p[2 * j], yy = p[2 * j + 1];
        sx[j] = xx; sy[j] = yy;
        sd[j] = __fadd_rn(__fmul_rn(xx, xx), __fmul_rn(yy, yy));  // add-form d2
    }
    __syncthreads();

    int warp = threadIdx.x >> 5, lane = threadIdx.x & 31;
    int q = blockIdx.x * (blockDim.x >> 5) + warp;

    float xi = sx[q], yi = sy[q], d2i = sd[q];
    const float INF = __int_as_float(0x7f800000);
    float d0 = INF, d1 = INF, d2 = INF, d3 = INF, d4 = INF;
    int   i0 = 0x7fffffff, i1 = 0x7fffffff, i2 = 0x7fffffff, i3 = 0x7fffffff, i4 = 0x7fffffff;

    for (int j = lane; j < NPTS; j += 32) {
        float dot  = __fmaf_rn(yi, sy[j], __fmul_rn(xi, sx[j]));  // fma-form dot
        float dist = __fadd_rn(__fadd_rn(d2i, sd[j]), -__fmul_rn(2.0f, dot));
        if (LTC(dist, j, d4, i4)) {
            d4 = dist; i4 = j;
            if (LTC(d4, i4, d3, i3)) { float tf = d3; d3 = d4; d4 = tf; int ti = i3; i3 = i4; i4 = ti; }
            if (LTC(d3, i3, d2, i2)) { float tf = d2; d2 = d3; d3 = tf; int ti = i2; i2 = i3; i3 = ti; }
            if (LTC(d2, i2, d1, i1)) { float tf = d1; d1 = d2; d2 = tf; int ti = i1; i1 = i2; i2 = ti; }
            if (LTC(d1, i1, d0, i0)) { float tf = d0; d0 = d1; d1 = tf; int ti = i0; i0 = i1; i1 = ti; }
        }
    }
#pragma unroll
    for (int k = 0; k < KNN; k++) {
        float od = d0; int oi = i0;
#pragma unroll
        for (int off = 16; off; off >>= 1) {
            float td = __shfl_down_sync(0xffffffffu, od, off);
            int   ti = __shfl_down_sync(0xffffffffu, oi, off);
            if (LTC(td, ti, od, oi)) { od = td; oi = ti; }
        }
        od = __shfl_sync(0xffffffffu, od, 0);
        oi = __shfl_sync(0xffffffffu, oi, 0);
        if (oi == i0) {
            d0 = d1; i0 = i1; d1 = d2; i1 = i2; d2 = d3; i2 = i3; d3 = d4; i3 = i4;
            d4 = INF; i4 = 0x7fffffff;
        }
        if (lane == 0) g_idx[((size_t)(b * NPTS + q)) * KNN + k] = oi;
    }
}

// ---------------- bn coefficients + stats reset (1 block, 512 threads) -----------
__global__ void bn_coef(const float* __restrict__ gamma, const float* __restrict__ beta) {
    int c = threadIdx.x;
    const float inv = 1.0f / (float)MROWS;
    float mean = g_sum[c] * inv;
    float var  = g_sumsq[c] * inv - mean * mean;
    float a = rsqrtf(var + 1e-5f) * gamma[c];
    g_bnA[c] = a;
    g_bnB[c] = beta[c] - mean * a;
    g_sum[c] = 0.f;       // re-zero for the next GEMM's fused stats
    g_sumsq[c] = 0.f;
}

// ---------------- feat (layer 1): 1 row per 128-thread block, float4 -------------
__global__ void feat_kernel() {
    __shared__ int nb[KNN];
    int r = blockIdx.x, tid = threadIdx.x;
    if (tid < KNN) nb[tid] = (r >> 12) * NPTS + g_idx[r * KNN + tid];
    __syncthreads();
    float4 s = ((const float4*)(g_xt + (size_t)r * CH))[tid];
    float4 m = make_float4(-1e30f, -1e30f, -1e30f, -1e30f);
#pragma unroll
    for (int k = 0; k < KNN; k++) {
        float4 v = ((const float4*)(g_xt + (size_t)nb[k] * CH))[tid];
        m.x = fmaxf(m.x, v.x - s.x); m.y = fmaxf(m.y, v.y - s.y);
        m.z = fmaxf(m.z, v.z - s.z); m.w = fmaxf(m.w, v.w - s.w);
    }
    float slx, mlx, sly, mly, slz, mlz, slw, mlw;
    uint4 hi, lo;
    hi.x = pack_pair(s.x, m.x, slx, mlx);
    hi.y = pack_pair(s.y, m.y, sly, mly);
    hi.z = pack_pair(s.z, m.z, slz, mlz);
    hi.w = pack_pair(s.w, m.w, slw, mlw);
    lo.x = pack_lo(slx, mlx); lo.y = pack_lo(sly, mly);
    lo.z = pack_lo(slz, mlz); lo.w = pack_lo(slw, mlw);
    ((uint4*)(g_Ahi + (size_t)r * KDIM))[tid] = hi;
    ((uint4*)(g_Alo + (size_t)r * KDIM))[tid] = lo;
}

// ---------------- bnfeat (layers 2,3): 1 row per 128-thread block, float4 --------
__global__ void bnfeat_kernel() {
    __shared__ int nb[KNN];
    int r = blockIdx.x, tid = threadIdx.x;
    if (tid < KNN) nb[tid] = (r >> 12) * NPTS + g_idx[r * KNN + tid];
    __syncthreads();
    float4 a = ((const float4*)g_bnA)[tid];
    float4 b = ((const float4*)g_bnB)[tid];
    float4 y = ((const float4*)(g_y + (size_t)r * CH))[tid];
    float4 s;
    s.x = fmaxf(fmaf(y.x, a.x, b.x), 0.f);
    s.y = fmaxf(fmaf(y.y, a.y, b.y), 0.f);
    s.z = fmaxf(fmaf(y.z, a.z, b.z), 0.f);
    s.w = fmaxf(fmaf(y.w, a.w, b.w), 0.f);
    float4 m = make_float4(-1e30f, -1e30f, -1e30f, -1e30f);
#pragma unroll
    for (int k = 0; k < KNN; k++) {
        float4 v = ((const float4*)(g_y + (size_t)nb[k] * CH))[tid];
        m.x = fmaxf(m.x, fmaxf(fmaf(v.x, a.x, b.x), 0.f) - s.x);
        m.y = fmaxf(m.y, fmaxf(fmaf(v.y, a.y, b.y), 0.f) - s.y);
        m.z = fmaxf(m.z, fmaxf(fmaf(v.z, a.z, b.z), 0.f) - s.z);
        m.w = fmaxf(m.w, fmaxf(fmaf(v.w, a.w, b.w), 0.f) - s.w);
    }
    float slx, mlx, sly, mly, slz, mlz, slw, mlw;
    uint4 hi, lo;
    hi.x = pack_pair(s.x, m.x, slx, mlx);
    hi.y = pack_pair(s.y, m.y, sly, mly);
    hi.z = pack_pair(s.z, m.z, slz, mlz);
    hi.w = pack_pair(s.w, m.w, slw, mlw);
    lo.x = pack_lo(slx, mlx); lo.y = pack_lo(sly, mly);
    lo.z = pack_lo(slz, mlz); lo.w = pack_lo(slw, mlw);
    ((uint4*)(g_Ahi + (size_t)r * KDIM))[tid] = hi;
    ((uint4*)(g_Alo + (size_t)r * KDIM))[tid] = lo;
}

// ---------------- bn_apply for classifier (layer 3 -> Xhi only), float4 ----------
__global__ void bn_apply_cls() {
    int i4 = blockIdx.x * blockDim.x + threadIdx.x;   // float4 index
    int c4 = i4 & 127;
    float4 a = ((const float4*)g_bnA)[c4];
    float4 b = ((const float4*)g_bnB)[c4];
    float4 y = ((const float4*)g_y)[i4];
    float vx = fmaxf(fmaf(y.x, a.x, b.x), 0.f);
    float vy = fmaxf(fmaf(y.y, a.y, b.y), 0.f);
    float vz = fmaxf(fmaf(y.z, a.z, b.z), 0.f);
    float vw = fmaxf(fmaf(y.w, a.w, b.w), 0.f);
    __half2 h0; h0.x = __float2half_rn(vx); h0.y = __float2half_rn(vy);
    __half2 h1; h1.x = __float2half_rn(vz); h1.y = __float2half_rn(vw);
    uint2 hv = make_uint2(*(uint32_t*)&h0, *(uint32_t*)&h1);
    ((uint2*)g_Xhi)[i4] = hv;
}

// ---------------- all weight conversions (fp16 hi only) + initial stats zero -----
#define W_ELEMS (CH * KDIM)
#define C_ELEMS ((CH / 2) * CH)
__global__ void wsplit_all(const float* __restrict__ w1, const float* __restrict__ w2,
                           const float* __restrict__ w3, const float* __restrict__ wc1) {
    int i = blockIdx.x * blockDim.x + threadIdx.x;
    if (i < CH) { g_sum[i] = 0.f; g_sumsq[i] = 0.f; }
    const float* src; __half* hi; int k;
    if (i < W_ELEMS)            { src = w1;  hi = g_Whi;               k = i; }
    else if (i < 2 * W_ELEMS)   { src = w2;  hi = g_Whi + W_ELEMS;     k = i - W_ELEMS; }
    else if (i < 3 * W_ELEMS)   { src = w3;  hi = g_Whi + 2 * W_ELEMS; k = i - 2 * W_ELEMS; }
    else if (i < 3 * W_ELEMS + C_ELEMS) { src = wc1; hi = g_Chi;       k = i - 3 * W_ELEMS; }
    else return;
    hi[k] = __float2half_rn(src[k]);
}

// ============ HMMA fp16 fused-term GEMM, 128x128 tile, 2-stage, 2 CTA/SM =========
// TERMS=2: C = (Ahi + Alo)*Bh^T + bias, both terms per K-chunk (B tile shared).
// TERMS=1: C = Ahi*Bh^T + bias.
// 8 warps (2M x 4N), warp 64x32. K chunks of 64 fp16.
// Stage = [Ahi 16K | (Alo 16K) | B 16K] = (TERMS+1)*16 KB; 2 stages.

template <int RELU, int STATS, int TERMS>
__global__ void __launch_bounds__(256, 2) mma_gemm(
    const __half* __restrict__ Ahi, const __half* __restrict__ Alo,
    const __half* __restrict__ Bh,
    const float* __restrict__ bias, float* __restrict__ C, int Kd, int Nn) {
    constexpr int STG = (TERMS + 1) * 16384;
    extern __shared__ char smem[];
    uint32_t sb = smem_u32(smem);
    int tid = threadIdx.x, lane = tid & 31, wid = tid >> 5;
    int wm = wid & 1, wn = wid >> 1;
    int row0 = blockIdx.y * 128, col0 = blockIdx.x * 128;
    int NIT = Kd >> 6;

    float acc[4][4][4];
#pragma unroll
    for (int mi = 0; mi < 4; mi++)
#pragma unroll
        for (int ni = 0; ni < 4; ni++)
#pragma unroll
            for (int j = 0; j < 4; j++) acc[mi][ni][j] = 0.f;

    int lr = tid >> 3, lg = tid & 7;

    auto load_chunk = [&](int kc, int st) {
        uint32_t abase = sb + st * STG;
        uint32_t bbase = abase + TERMS * 16384;
#pragma unroll
        for (int i = 0; i < 4; i++) {
            int r = lr + i * 32;
            CP_ASYNC16(abase + SWZ((uint32_t)(r * 128 + lg * 16)),
                       Ahi + (size_t)(row0 + r) * Kd + kc * 64 + lg * 8);
        }
        if (TERMS == 2) {
            uint32_t lbase = abase + 16384;
#pragma unroll
            for (int i = 0; i < 4; i++) {
                int r = lr + i * 32;
                CP_ASYNC16(lbase + SWZ((uint32_t)(r * 128 + lg * 16)),
                           Alo + (size_t)(row0 + r) * Kd + kc * 64 + lg * 8);
            }
        }
#pragma unroll
        for (int i = 0; i < 4; i++) {
            int r = lr + i * 32;
            CP_ASYNC16(bbase + SWZ((uint32_t)(r * 128 + lg * 16)),
                       Bh + (size_t)(col0 + r) * Kd + kc * 64 + lg * 8);
        }
        CP_COMMIT();
    };

    load_chunk(0, 0);
    load_chunk(1, 1);

    for (int it = 0; it < NIT; it++) {
        int s = it & 1;
        if (it + 1 < NIT) { CP_WAIT1(); } else { CP_WAIT0(); }
        __syncthreads();

        uint32_t abase = sb + s * STG;
        uint32_t bbase = abase + TERMS * 16384;
#pragma unroll
        for (int kk = 0; kk < 4; kk++) {
            uint32_t bfr[4][2];
#pragma unroll
            for (int ni = 0; ni < 4; ni++) {
                int r = wn * 32 + ni * 8 + (lane & 7);
                uint32_t off = (uint32_t)(r * 128 + kk * 32 + ((lane >> 3) & 1) * 16);
                ldsm_x2(bfr[ni], bbase + SWZ(off));
            }
#pragma unroll
            for (int t = 0; t < TERMS; t++) {
                uint32_t tbase = abase + t * 16384;
                uint32_t af[4][4];
#pragma unroll
                for (int mi = 0; mi < 4; mi++) {
                    int r = wm * 64 + mi * 16 + (lane & 15);
                    uint32_t off = (uint32_t)(r * 128 + kk * 32 + (lane >> 4) * 16);
                    ldsm_x4(af[mi], tbase + SWZ(off));
                }
#pragma unroll
                for (int ni = 0; ni < 4; ni++)
#pragma unroll
                    for (int mi = 0; mi < 4; mi++)
                        mma16816(acc[mi][ni], af[mi], bfr[ni][0], bfr[ni][1]);
            }
        }
        __syncthreads();
        if (it + 2 < NIT) load_chunk(it + 2, s);
    }

    // epilogue: +bias, optional relu, store; optional fused column stats
    float s_[4][2], q_[4][2];
    if (STATS) {
#pragma unroll
        for (int ni = 0; ni < 4; ni++) { s_[ni][0] = s_[ni][1] = q_[ni][0] = q_[ni][1] = 0.f; }
    }
#pragma unroll
    for (int mi = 0; mi < 4; mi++) {
        int row = row0 + wm * 64 + mi * 16 + (lane >> 2);
#pragma unroll
        for (int ni = 0; ni < 4; ni++) {
            int col = col0 + wn * 32 + ni * 8 + (lane & 3) * 2;
            float b0 = bias[col], b1 = bias[col + 1];
            float v0 = acc[mi][ni][0] + b0, v1 = acc[mi][ni][1] + b1;
            float v2 = acc[mi][ni][2] + b0, v3 = acc[mi][ni][3] + b1;
            if (RELU) {
                v0 = fmaxf(v0, 0.f); v1 = fmaxf(v1, 0.f);
                v2 = fmaxf(v2, 0.f); v3 = fmaxf(v3, 0.f);
            }
            if (STATS) {
                s_[ni][0] += v0 + v2; s_[ni][1] += v1 + v3;
                q_[ni][0] += v0 * v0 + v2 * v2; q_[ni][1] += v1 * v1 + v3 * v3;
            }
            *(float2*)(C + (size_t)row * Nn + col) = make_float2(v0, v1);
            *(float2*)(C + (size_t)(row + 8) * Nn + col) = make_float2(v2, v3);
        }
    }
    if (STATS) {
#pragma unroll
        for (int ni = 0; ni < 4; ni++) {
#pragma unroll
            for (int j = 0; j < 2; j++) {
#pragma unroll
                for (int off = 4; off <= 16; off <<= 1) {
                    s_[ni][j] += __shfl_xor_sync(0xffffffffu, s_[ni][j], off);
                    q_[ni][j] += __shfl_xor_sync(0xffffffffu, q_[ni][j], off);
                }
            }
        }
        if ((lane >> 2) == 0) {
#pragma unroll
            for (int ni = 0; ni < 4; ni++) {
                int col = col0 + wn * 32 + ni * 8 + (lane & 3) * 2;
                atomicAdd(&g_sum[col],     s_[ni][0]);
                atomicAdd(&g_sum[col + 1], s_[ni][1]);
                atomicAdd(&g_sumsq[col],     q_[ni][0]);
                atomicAdd(&g_sumsq[col + 1], q_[ni][1]);
            }
        }
    }
}

// ---------------- final tiny GEMM: out[M,5] = h[M,256] @ Wc2[5,256]^T + bc2 -----
__global__ void final_kernel(const float* __restrict__ Wc2, const float* __restrict__ bc2,
                             float* __restrict__ out) {
    __shared__ float w[5 * 256];
    for (int i = threadIdx.x; i < 5 * 256; i += blockDim.x) w[i] = Wc2[i];
    __syncthreads();
    int warp = threadIdx.x >> 5, lane = threadIdx.x & 31;
    int r = blockIdx.x * (blockDim.x >> 5) + warp;
    const float* h = g_h + (size_t)r * 256;
    float a0 = 0, a1 = 0, a2 = 0, a3 = 0, a4 = 0;
    for (int c = lane; c < 256; c += 32) {
        float hv = h[c];
        a0 = fmaf(hv, w[0 * 256 + c], a0);
        a1 = fmaf(hv, w[1 * 256 + c], a1);
        a2 = fmaf(hv, w[2 * 256 + c], a2);
        a3 = fmaf(hv, w[3 * 256 + c], a3);
        a4 = fmaf(hv, w[4 * 256 + c], a4);
    }
#pragma unroll
    for (int off = 16; off; off >>= 1) {
        a0 += __shfl_xor_sync(0xffffffffu, a0, off);
        a1 += __shfl_xor_sync(0xffffffffu, a1, off);
        a2 += __shfl_xor_sync(0xffffffffu, a2, off);
        a3 += __shfl_xor_sync(0xffffffffu, a3, off);
        a4 += __shfl_xor_sync(0xffffffffu, a4, off);
    }
    if (lane == 0) {
        float* o = out + (size_t)r * 5;
        o[0] = a0 + bc2[0];
        o[1] = a1 + bc2[1];
        o[2] = a2 + bc2[2];
        o[3] = a3 + bc2[3];
        o[4] = a4 + bc2[4];
    }
}

// ---------------- launch ----------------
extern "C" void kernel_launch(void* const* d_in, const int* in_sizes, int n_in,
                              void* d_out, int out_size) {
    const float* x    = (const float*)d_in[0];
    const float* pos  = (const float*)d_in[1];
    const float* W[3]  = {(const float*)d_in[2], (const float*)d_in[6], (const float*)d_in[10]};
    const float* bb[3] = {(const float*)d_in[3], (const float*)d_in[7], (const float*)d_in[11]};
    const float* gg[3] = {(const float*)d_in[4], (const float*)d_in[8], (const float*)d_in[12]};
    const float* be[3] = {(const float*)d_in[5], (const float*)d_in[9], (const float*)d_in[13]};
    const float* Wc1 = (const float*)d_in[14];
    const float* bc1 = (const float*)d_in[15];
    const float* Wc2 = (const float*)d_in[16];
    const float* bc2 = (const float*)d_in[17];
    float* out = (float*)d_out;

    float *p_y, *p_h;
    __half *p_Ahi, *p_Alo, *p_Xhi, *p_Whi, *p_Chi;
    cudaGetSymbolAddress((void**)&p_y, g_y);
    cudaGetSymbolAddress((void**)&p_h, g_h);
    cudaGetSymbolAddress((void**)&p_Ahi, g_Ahi);
    cudaGetSymbolAddress((void**)&p_Alo, g_Alo);
    cudaGetSymbolAddress((void**)&p_Xhi, g_Xhi);
    cudaGetSymbolAddress((void**)&p_Whi, g_Whi);
    cudaGetSymbolAddress((void**)&p_Chi, g_Chi);

    cudaFuncSetAttribute(mma_gemm<0, 1, 2>, cudaFuncAttributeMaxDynamicSharedMemorySize, 2 * 3 * 16384);
    cudaFuncSetAttribute(mma_gemm<1, 0, 1>, cudaFuncAttributeMaxDynamicSharedMemorySize, 2 * 2 * 16384);

    transpose_kernel<<<dim3(NPTS / 32, CH / 32, BATCH), dim3(32, 8)>>>(x);
    knn_kernel<<<dim3(NPTS / 8, BATCH), 256>>>(pos);
    wsplit_all<<<(3 * W_ELEMS + C_ELEMS) / 256, 256>>>(W[0], W[1], W[2], Wc1);

    for (int i = 0; i < 3; i++) {
        if (i == 0) feat_kernel<<<MROWS, 128>>>();
        else        bnfeat_kernel<<<MROWS, 128>>>();
        mma_gemm<0, 1, 2><<<dim3(CH / 128, MROWS / 128), 256, 2 * 3 * 16384>>>(
            p_Ahi, p_Alo, p_Whi + (size_t)i * CH * KDIM,
            bb[i], p_y, KDIM, CH);
        bn_coef<<<1, CH>>>(gg[i], be[i]);
    }

    // classifier: Xhi = bn+relu(layer3), then h = relu(X @ Wc1^T + bc1) (1-term)
    bn_apply_cls<<<(MROWS * CH / 4) / 256, 256>>>();
    mma_gemm<1, 0, 1><<<dim3((CH / 2) / 128, MROWS / 128), 256, 2 * 2 * 16384>>>(
        p_Xhi, p_Xhi, p_Chi, bc1, p_h, CH, CH / 2);
    final_kernel<<<MROWS / 8, 256>>>(Wc2, bc2, out);
}